// round 1
// baseline (speedup 1.0000x reference)
#include <cuda_runtime.h>
#include <float.h>

// Problem dims (fixed by the reference)
static constexpr int B_  = 32;
static constexpr int TQ  = 1024;
static constexpr int TK  = 1024;
static constexpr int HH  = 512;

// GEMM tiling
#define BM 128
#define BN 128
#define BK 16
#define PAD 4   // smem row padding (keeps 16B alignment: (BM+4)=132, 132%4==0)

// ---------------------------------------------------------------------------
// C = A * B^T (+ optional bias broadcast over rows)
// A: [M,K] row-major, B: [N,K] row-major  (both K-contiguous)
// Batched via blockIdx.z with given element strides.
// Requires M%BM==0, N%BN==0, K%BK==0 (true for all our shapes).
// ---------------------------------------------------------------------------
template <bool ADD_BIAS>
__global__ __launch_bounds__(256, 2)
void gemm_nt(const float* __restrict__ A, const float* __restrict__ Bm,
             const float* __restrict__ bias, float* __restrict__ C,
             int M, int N, int K,
             long long sA, long long sB, long long sC)
{
    __shared__ float As[BK][BM + PAD];
    __shared__ float Bs[BK][BN + PAD];

    const float* Ab = A  + (long long)blockIdx.z * sA;
    const float* Bb = Bm + (long long)blockIdx.z * sB;
    float*       Cb = C  + (long long)blockIdx.z * sC;

    const int m0  = blockIdx.y * BM;
    const int n0  = blockIdx.x * BN;
    const int tid = threadIdx.x;           // 256 threads

    // global->smem loading layout (transpose into [k][m])
    const int lr = tid >> 2;                // 0..63 (row within half-tile)
    const int lc = (tid & 3) << 2;          // k offset: 0,4,8,12

    // compute microtile layout: 16x16 threads, each 8x8
    const int tm = (tid >> 4) << 3;         // 0..120
    const int tn = (tid & 15) << 3;         // 0..120

    float acc[8][8] = {};

    for (int k0 = 0; k0 < K; k0 += BK) {
        #pragma unroll
        for (int r = 0; r < 2; r++) {
            const int row = lr + r * 64;
            float4 av = *(const float4*)(Ab + (long long)(m0 + row) * K + k0 + lc);
            float4 bv = *(const float4*)(Bb + (long long)(n0 + row) * K + k0 + lc);
            As[lc + 0][row] = av.x; As[lc + 1][row] = av.y;
            As[lc + 2][row] = av.z; As[lc + 3][row] = av.w;
            Bs[lc + 0][row] = bv.x; Bs[lc + 1][row] = bv.y;
            Bs[lc + 2][row] = bv.z; Bs[lc + 3][row] = bv.w;
        }
        __syncthreads();

        #pragma unroll
        for (int k = 0; k < BK; k++) {
            float a[8], b[8];
            *(float4*)&a[0] = *(const float4*)&As[k][tm];
            *(float4*)&a[4] = *(const float4*)&As[k][tm + 4];
            *(float4*)&b[0] = *(const float4*)&Bs[k][tn];
            *(float4*)&b[4] = *(const float4*)&Bs[k][tn + 4];
            #pragma unroll
            for (int i = 0; i < 8; i++)
                #pragma unroll
                for (int j = 0; j < 8; j++)
                    acc[i][j] += a[i] * b[j];
        }
        __syncthreads();
    }

    #pragma unroll
    for (int i = 0; i < 8; i++) {
        const long long m = m0 + tm + i;
        #pragma unroll
        for (int j = 0; j < 8; j += 4) {
            float4 v;
            v.x = acc[i][j + 0]; v.y = acc[i][j + 1];
            v.z = acc[i][j + 2]; v.w = acc[i][j + 3];
            if (ADD_BIAS) {
                v.x += bias[n0 + tn + j + 0];
                v.y += bias[n0 + tn + j + 1];
                v.z += bias[n0 + tn + j + 2];
                v.w += bias[n0 + tn + j + 3];
            }
            *(float4*)(Cb + m * N + n0 + tn + j) = v;
        }
    }
}

// ---------------------------------------------------------------------------
// C = A * B   A: [M,K] row-major, B: [K,N] row-major. Batched via blockIdx.z.
// ---------------------------------------------------------------------------
__global__ __launch_bounds__(256, 2)
void gemm_nn(const float* __restrict__ A, const float* __restrict__ Bm,
             float* __restrict__ C,
             int M, int N, int K,
             long long sA, long long sB, long long sC)
{
    __shared__ float As[BK][BM + PAD];
    __shared__ float Bs[BK][BN + PAD];

    const float* Ab = A  + (long long)blockIdx.z * sA;
    const float* Bb = Bm + (long long)blockIdx.z * sB;
    float*       Cb = C  + (long long)blockIdx.z * sC;

    const int m0  = blockIdx.y * BM;
    const int n0  = blockIdx.x * BN;
    const int tid = threadIdx.x;

    const int lrA = tid >> 2;               // 0..63
    const int lcA = (tid & 3) << 2;         // 0,4,8,12
    const int lrB = tid >> 5;               // 0..7
    const int lcB = (tid & 31) << 2;        // 0..124

    const int tm = (tid >> 4) << 3;
    const int tn = (tid & 15) << 3;

    float acc[8][8] = {};

    for (int k0 = 0; k0 < K; k0 += BK) {
        #pragma unroll
        for (int r = 0; r < 2; r++) {
            const int row = lrA + r * 64;
            float4 av = *(const float4*)(Ab + (long long)(m0 + row) * K + k0 + lcA);
            As[lcA + 0][row] = av.x; As[lcA + 1][row] = av.y;
            As[lcA + 2][row] = av.z; As[lcA + 3][row] = av.w;
        }
        #pragma unroll
        for (int r = 0; r < 2; r++) {
            const int rowb = lrB + r * 8;   // k within tile: 0..15
            float4 bv = *(const float4*)(Bb + (long long)(k0 + rowb) * N + n0 + lcB);
            *(float4*)&Bs[rowb][lcB] = bv;
        }
        __syncthreads();

        #pragma unroll
        for (int k = 0; k < BK; k++) {
            float a[8], b[8];
            *(float4*)&a[0] = *(const float4*)&As[k][tm];
            *(float4*)&a[4] = *(const float4*)&As[k][tm + 4];
            *(float4*)&b[0] = *(const float4*)&Bs[k][tn];
            *(float4*)&b[4] = *(const float4*)&Bs[k][tn + 4];
            #pragma unroll
            for (int i = 0; i < 8; i++)
                #pragma unroll
                for (int j = 0; j < 8; j++)
                    acc[i][j] += a[i] * b[j];
        }
        __syncthreads();
    }

    #pragma unroll
    for (int i = 0; i < 8; i++) {
        const long long m = m0 + tm + i;
        #pragma unroll
        for (int j = 0; j < 8; j += 4) {
            float4 v;
            v.x = acc[i][j + 0]; v.y = acc[i][j + 1];
            v.z = acc[i][j + 2]; v.w = acc[i][j + 3];
            *(float4*)(Cb + m * N + n0 + tn + j) = v;
        }
    }
}

// ---------------------------------------------------------------------------
// In-place row softmax over TK=1024 columns. One 256-thread block per row,
// each thread owns one float4.
// ---------------------------------------------------------------------------
__global__ __launch_bounds__(256)
void softmax_rows(float* __restrict__ attn)
{
    const long long row = blockIdx.x;
    float* p = attn + row * (long long)TK;
    const int tid = threadIdx.x;

    float4 v = reinterpret_cast<float4*>(p)[tid];

    __shared__ float sred[8];

    // ---- max ----
    float m = fmaxf(fmaxf(v.x, v.y), fmaxf(v.z, v.w));
    #pragma unroll
    for (int o = 16; o > 0; o >>= 1)
        m = fmaxf(m, __shfl_xor_sync(0xffffffffu, m, o));
    if ((tid & 31) == 0) sred[tid >> 5] = m;
    __syncthreads();
    if (tid < 32) {
        float t = (tid < 8) ? sred[tid] : -FLT_MAX;
        #pragma unroll
        for (int o = 4; o > 0; o >>= 1)
            t = fmaxf(t, __shfl_xor_sync(0xffffffffu, t, o));
        if (tid == 0) sred[0] = t;
    }
    __syncthreads();
    const float mx = sred[0];
    __syncthreads();

    // ---- exp + sum ----
    v.x = __expf(v.x - mx);
    v.y = __expf(v.y - mx);
    v.z = __expf(v.z - mx);
    v.w = __expf(v.w - mx);
    float s = v.x + v.y + v.z + v.w;
    #pragma unroll
    for (int o = 16; o > 0; o >>= 1)
        s += __shfl_xor_sync(0xffffffffu, s, o);
    if ((tid & 31) == 0) sred[tid >> 5] = s;
    __syncthreads();
    if (tid < 32) {
        float t = (tid < 8) ? sred[tid] : 0.0f;
        #pragma unroll
        for (int o = 4; o > 0; o >>= 1)
            t += __shfl_xor_sync(0xffffffffu, t, o);
        if (tid == 0) sred[0] = t;
    }
    __syncthreads();
    const float inv = 1.0f / sred[0];

    v.x *= inv; v.y *= inv; v.z *= inv; v.w *= inv;
    reinterpret_cast<float4*>(p)[tid] = v;
}

// ---------------------------------------------------------------------------
// Launch
// Inputs (metadata order): query [B,Tq,H], keys [B,Tk,H], W [H,H], b [H]
// Output: context [B,Tq,H] then attn_weights [B,Tq,Tk], contiguous in d_out.
// The q = query@W^T+b intermediate is staged in the context region (same
// size), consumed by the scores GEMM, then overwritten by the final GEMM.
// ---------------------------------------------------------------------------
extern "C" void kernel_launch(void* const* d_in, const int* in_sizes, int n_in,
                              void* d_out, int out_size)
{
    const float* query = (const float*)d_in[0];
    const float* keys  = (const float*)d_in[1];
    const float* W     = (const float*)d_in[2];
    const float* bias  = (const float*)d_in[3];

    float* ctx  = (float*)d_out;                          // [B,Tq,H]
    float* attn = ctx + (long long)B_ * TQ * HH;          // [B,Tq,Tk]

    dim3 blk(256);

    // 1) q = query @ W^T + b   (flattened [B*Tq, H] x [H, H]^T) -> ctx scratch
    gemm_nt<true><<<dim3(HH / BN, (B_ * TQ) / BM, 1), blk>>>(
        query, W, bias, ctx,
        B_ * TQ, HH, HH, 0, 0, 0);

    // 2) scores = q @ keys^T per batch -> attn region
    gemm_nt<false><<<dim3(TK / BN, TQ / BM, B_), blk>>>(
        ctx, keys, nullptr, attn,
        TQ, TK, HH,
        (long long)TQ * HH, (long long)TK * HH, (long long)TQ * TK);

    // 3) softmax rows in place
    softmax_rows<<<B_ * TQ, 256>>>(attn);

    // 4) context = attn @ keys per batch -> ctx (overwrites q scratch)
    gemm_nn<<<dim3(HH / BN, TQ / BM, B_), blk>>>(
        attn, keys, ctx,
        TQ, HH, TK,
        (long long)TQ * TK, (long long)TK * HH, (long long)TQ * HH);
}

// round 3
// speedup vs baseline: 1.3054x; 1.3054x over previous
#include <cuda_runtime.h>
#include <float.h>
#include <stdint.h>

// Problem dims (fixed by the reference)
static constexpr int B_  = 32;
static constexpr int TQ  = 1024;
static constexpr int TK  = 1024;
static constexpr int HH  = 512;

// ---------------------------------------------------------------------------
// mma.sync tf32 GEMM (sm_80+ PTX, legal under compute_103):
//   C[M,N] = A[M,K] * B[N,K]^T (+ bias over N), fp32 in/out.
// CTA tile 128x128, K-stage 32. 8 warps, each 64(m) x 32(n).
// 3xTF32 split for fp32 accuracy: D += Ahi*Bhi + Ahi*Blo + Alo*Bhi.
// ---------------------------------------------------------------------------
static constexpr int BM = 128;
static constexpr int BN = 128;
static constexpr int BK = 32;
static constexpr int PADK = 36;                 // floats per smem row (32 + 4 pad)
static constexpr int TILE_FLOATS = 128 * PADK;  // 4608 floats = 18432 B per operand
static constexpr int STAGE_BYTES = 2 * TILE_FLOATS * 4;   // A + B = 36864 B
static constexpr int SMEM_BYTES  = 2 * STAGE_BYTES;       // double buffered = 72 KB

__device__ float g_keysT[(size_t)B_ * HH * TK];  // 64MB scratch: keys^T [B,H,Tk]

__device__ __forceinline__ uint32_t smem_u32_of(const void* p) {
    uint32_t a;
    asm("{ .reg .u64 t; cvta.to.shared.u64 t, %1; cvt.u32.u64 %0, t; }"
        : "=r"(a) : "l"(p));
    return a;
}

__device__ __forceinline__ uint32_t f2tf32(float x) {
    uint32_t u;
    asm("cvt.rna.tf32.f32 %0, %1;" : "=r"(u) : "f"(x));
    return u;
}

__device__ __forceinline__ void cp_async16(uint32_t dst_smem, const void* src) {
    asm volatile("cp.async.cg.shared.global [%0], [%1], 16;"
                 :: "r"(dst_smem), "l"(src) : "memory");
}

__device__ __forceinline__ void mma_tf32(float* d, const uint32_t* a, const uint32_t* b) {
    asm volatile(
        "mma.sync.aligned.m16n8k8.row.col.f32.tf32.tf32.f32 "
        "{%0,%1,%2,%3}, {%4,%5,%6,%7}, {%8,%9}, {%0,%1,%2,%3};"
        : "+f"(d[0]), "+f"(d[1]), "+f"(d[2]), "+f"(d[3])
        : "r"(a[0]), "r"(a[1]), "r"(a[2]), "r"(a[3]), "r"(b[0]), "r"(b[1]));
}

template <bool ADD_BIAS>
__global__ __launch_bounds__(256, 1)
void mma_gemm_nt(const float* __restrict__ A, const float* __restrict__ Bm,
                 const float* __restrict__ bias, float* __restrict__ C,
                 int M, int N, int K,
                 long long sA, long long sB, long long sC)
{
    extern __shared__ float sm[];
    const uint32_t smem_base = smem_u32_of(sm);

    const int tid  = threadIdx.x;
    const int wid  = tid >> 5;
    const int lane = tid & 31;
    const int grp  = lane >> 2;      // 0..7
    const int quad = lane & 3;       // 0..3

    const int wm = (wid & 1) * 64;   // warp m-offset in CTA tile
    const int wn = (wid >> 1) * 32;  // warp n-offset in CTA tile

    const float* Ab = A  + (long long)blockIdx.z * sA;
    const float* Bb = Bm + (long long)blockIdx.z * sB;
    float*       Cb = C  + (long long)blockIdx.z * sC;
    const int m0 = blockIdx.y * BM;
    const int n0 = blockIdx.x * BN;
    const int S  = K / BK;

    // Stage loader: 256 threads, each 4 float4 per operand.
    // f = tid + i*256; row = f>>3 (0..127), j = f&7 (float4 column).
    const int lrow = tid >> 3;
    const int lj4  = (tid & 7) * 4;
    auto load_stage = [&](int s, int buf) {
        const int k0 = s * BK;
        const uint32_t sb = smem_base + (uint32_t)(buf * STAGE_BYTES);
        #pragma unroll
        for (int i = 0; i < 4; ++i) {
            const int row = lrow + i * 32;
            cp_async16(sb + (uint32_t)((row * PADK + lj4) * 4),
                       Ab + (long long)(m0 + row) * K + k0 + lj4);
        }
        #pragma unroll
        for (int i = 0; i < 4; ++i) {
            const int row = lrow + i * 32;
            cp_async16(sb + (uint32_t)((TILE_FLOATS + row * PADK + lj4) * 4),
                       Bb + (long long)(n0 + row) * K + k0 + lj4);
        }
        asm volatile("cp.async.commit_group;" ::: "memory");
    };

    float acc[4][4][4] = {};   // [mf][nf][c0..c3]

    load_stage(0, 0);

    for (int s = 0; s < S; ++s) {
        const int buf = s & 1;
        if (s + 1 < S) {
            load_stage(s + 1, buf ^ 1);
            asm volatile("cp.async.wait_group 1;" ::: "memory");
        } else {
            asm volatile("cp.async.wait_group 0;" ::: "memory");
        }
        __syncthreads();

        const float* As = sm + buf * (STAGE_BYTES / 4);
        const float* Bs = As + TILE_FLOATS;

        #pragma unroll
        for (int k8 = 0; k8 < BK / 8; ++k8) {
            const int kb = k8 * 8;
            uint32_t ah[4][4], al[4][4];
            uint32_t bh[4][2], bl[4][2];
            #pragma unroll
            for (int mf = 0; mf < 4; ++mf) {
                const int r = wm + mf * 16 + grp;
                const float* p = As + r * PADK + kb + quad;
                float a0 = p[0];
                float a1 = p[8 * PADK];
                float a2 = p[4];
                float a3 = p[8 * PADK + 4];
                ah[mf][0] = f2tf32(a0); al[mf][0] = f2tf32(a0 - __uint_as_float(ah[mf][0]));
                ah[mf][1] = f2tf32(a1); al[mf][1] = f2tf32(a1 - __uint_as_float(ah[mf][1]));
                ah[mf][2] = f2tf32(a2); al[mf][2] = f2tf32(a2 - __uint_as_float(ah[mf][2]));
                ah[mf][3] = f2tf32(a3); al[mf][3] = f2tf32(a3 - __uint_as_float(ah[mf][3]));
            }
            #pragma unroll
            for (int nf = 0; nf < 4; ++nf) {
                const int n = wn + nf * 8 + grp;
                const float* p = Bs + n * PADK + kb + quad;
                float b0 = p[0];
                float b1 = p[4];
                bh[nf][0] = f2tf32(b0); bl[nf][0] = f2tf32(b0 - __uint_as_float(bh[nf][0]));
                bh[nf][1] = f2tf32(b1); bl[nf][1] = f2tf32(b1 - __uint_as_float(bh[nf][1]));
            }
            #pragma unroll
            for (int mf = 0; mf < 4; ++mf)
                #pragma unroll
                for (int nf = 0; nf < 4; ++nf) {
                    mma_tf32(acc[mf][nf], ah[mf], bh[nf]);
                    mma_tf32(acc[mf][nf], ah[mf], bl[nf]);
                    mma_tf32(acc[mf][nf], al[mf], bh[nf]);
                }
        }
        __syncthreads();
    }

    // Epilogue: frag (mf,nf): c0,c1 -> row grp, cols quad*2+{0,1}; c2,c3 -> row grp+8.
    #pragma unroll
    for (int mf = 0; mf < 4; ++mf) {
        #pragma unroll
        for (int nf = 0; nf < 4; ++nf) {
            const int r = m0 + wm + mf * 16 + grp;
            const int c = n0 + wn + nf * 8 + quad * 2;
            float2 v0, v1;
            v0.x = acc[mf][nf][0]; v0.y = acc[mf][nf][1];
            v1.x = acc[mf][nf][2]; v1.y = acc[mf][nf][3];
            if (ADD_BIAS) {
                v0.x += bias[c]; v0.y += bias[c + 1];
                v1.x += bias[c]; v1.y += bias[c + 1];
            }
            *(float2*)(Cb + (long long)r * N + c) = v0;
            *(float2*)(Cb + (long long)(r + 8) * N + c) = v1;
        }
    }
}

// ---------------------------------------------------------------------------
// keys [B,Tk,H] -> keysT [B,H,Tk]
// ---------------------------------------------------------------------------
__global__ __launch_bounds__(256)
void transpose_keys(const float* __restrict__ in, float* __restrict__ out)
{
    __shared__ float tile[32][33];
    const int b  = blockIdx.z;
    const int t0 = blockIdx.x * 32;
    const int h0 = blockIdx.y * 32;
    const int tx = threadIdx.x;
    const int ty = threadIdx.y;
    const float* inb = in  + (long long)b * TK * HH;
    float*      outb = out + (long long)b * HH * TK;
    #pragma unroll
    for (int i = 0; i < 32; i += 8)
        tile[ty + i][tx] = inb[(long long)(t0 + ty + i) * HH + h0 + tx];
    __syncthreads();
    #pragma unroll
    for (int i = 0; i < 32; i += 8)
        outb[(long long)(h0 + ty + i) * TK + t0 + tx] = tile[tx][ty + i];
}

// ---------------------------------------------------------------------------
// In-place row softmax over TK=1024 columns.
// ---------------------------------------------------------------------------
__global__ __launch_bounds__(256)
void softmax_rows(float* __restrict__ attn)
{
    const long long row = blockIdx.x;
    float* p = attn + row * (long long)TK;
    const int tid = threadIdx.x;

    float4 v = reinterpret_cast<float4*>(p)[tid];
    __shared__ float sred[8];

    float m = fmaxf(fmaxf(v.x, v.y), fmaxf(v.z, v.w));
    #pragma unroll
    for (int o = 16; o > 0; o >>= 1)
        m = fmaxf(m, __shfl_xor_sync(0xffffffffu, m, o));
    if ((tid & 31) == 0) sred[tid >> 5] = m;
    __syncthreads();
    if (tid < 32) {
        float t = (tid < 8) ? sred[tid] : -FLT_MAX;
        #pragma unroll
        for (int o = 4; o > 0; o >>= 1)
            t = fmaxf(t, __shfl_xor_sync(0xffffffffu, t, o));
        if (tid == 0) sred[0] = t;
    }
    __syncthreads();
    const float mx = sred[0];
    __syncthreads();

    v.x = __expf(v.x - mx);
    v.y = __expf(v.y - mx);
    v.z = __expf(v.z - mx);
    v.w = __expf(v.w - mx);
    float s = v.x + v.y + v.z + v.w;
    #pragma unroll
    for (int o = 16; o > 0; o >>= 1)
        s += __shfl_xor_sync(0xffffffffu, s, o);
    if ((tid & 31) == 0) sred[tid >> 5] = s;
    __syncthreads();
    if (tid < 32) {
        float t = (tid < 8) ? sred[tid] : 0.0f;
        #pragma unroll
        for (int o = 4; o > 0; o >>= 1)
            t += __shfl_xor_sync(0xffffffffu, t, o);
        if (tid == 0) sred[0] = t;
    }
    __syncthreads();
    const float inv = 1.0f / sred[0];

    v.x *= inv; v.y *= inv; v.z *= inv; v.w *= inv;
    reinterpret_cast<float4*>(p)[tid] = v;
}

// ---------------------------------------------------------------------------
// Launch. Inputs: query [B,Tq,H], keys [B,Tk,H], W [H,H], b [H]
// Output: context [B,Tq,H] then attn_weights [B,Tq,Tk].
// q intermediate staged in context region; keys^T in __device__ scratch.
// ---------------------------------------------------------------------------
extern "C" void kernel_launch(void* const* d_in, const int* in_sizes, int n_in,
                              void* d_out, int out_size)
{
    const float* query = (const float*)d_in[0];
    const float* keys  = (const float*)d_in[1];
    const float* W     = (const float*)d_in[2];
    const float* bias  = (const float*)d_in[3];

    float* ctx  = (float*)d_out;                     // [B,Tq,H]
    float* attn = ctx + (long long)B_ * TQ * HH;     // [B,Tq,Tk]

    float* keysT = nullptr;
    cudaGetSymbolAddress((void**)&keysT, g_keysT);

    cudaFuncSetAttribute((const void*)mma_gemm_nt<true>,
                         cudaFuncAttributeMaxDynamicSharedMemorySize, SMEM_BYTES);
    cudaFuncSetAttribute((const void*)mma_gemm_nt<false>,
                         cudaFuncAttributeMaxDynamicSharedMemorySize, SMEM_BYTES);

    // 0) keysT = transpose(keys)
    transpose_keys<<<dim3(TK / 32, HH / 32, B_), dim3(32, 8)>>>(keys, keysT);

    // 1) q = query @ W^T + b  -> ctx scratch  [32768, 512]
    mma_gemm_nt<true><<<dim3(HH / BN, (B_ * TQ) / BM, 1), 256, SMEM_BYTES>>>(
        query, W, bias, ctx, B_ * TQ, HH, HH, 0, 0, 0);

    // 2) scores = q @ keys^T per batch -> attn [B,1024,1024]
    mma_gemm_nt<false><<<dim3(TK / BN, TQ / BM, B_), 256, SMEM_BYTES>>>(
        ctx, keys, nullptr, attn, TQ, TK, HH,
        (long long)TQ * HH, (long long)TK * HH, (long long)TQ * TK);

    // 3) softmax rows in place
    softmax_rows<<<B_ * TQ, 256>>>(attn);

    // 4) context = attn @ keysT^T per batch -> ctx
    mma_gemm_nt<false><<<dim3(HH / BN, TQ / BM, B_), 256, SMEM_BYTES>>>(
        attn, keysT, nullptr, ctx, TQ, HH, TK,
        (long long)TQ * TK, (long long)HH * TK, (long long)TQ * HH);
}

// round 4
// speedup vs baseline: 1.4007x; 1.0731x over previous
#include <cuda_runtime.h>
#include <float.h>
#include <stdint.h>

// Problem dims (fixed by the reference)
static constexpr int B_  = 32;
static constexpr int TQ  = 1024;
static constexpr int TK  = 1024;
static constexpr int HH  = 512;

// ---------------------------------------------------------------------------
// mma.sync tf32 GEMM: C[M,N] = A[M,K]*B[N,K]^T (+bias). fp32 in/out.
// CTA 128x128, K-stage 32, 8 warps each 64x32.
// 3xTF32: D += Ahi*Bhi + Ahi*Blo + Alo*Bhi, hi/lo precomputed in smem.
// ---------------------------------------------------------------------------
static constexpr int BM = 128;
static constexpr int BN = 128;
static constexpr int BK = 32;
static constexpr int PADK = 36;                       // floats per smem row
static constexpr int TILE_FLOATS  = 128 * PADK;       // 4608 floats per tile
static constexpr int STAGE_FLOATS = 4 * TILE_FLOATS;  // Ahi,Alo,Bhi,Blo = 18432
static constexpr int A_HI = 0;
static constexpr int A_LO = TILE_FLOATS;
static constexpr int B_HI = 2 * TILE_FLOATS;
static constexpr int B_LO = 3 * TILE_FLOATS;
static constexpr int SMEM_BYTES = 2 * STAGE_FLOATS * 4;   // 147456 B

__device__ float g_keysT[(size_t)B_ * HH * TK];  // 64MB scratch: keys^T [B,H,Tk]

__device__ __forceinline__ uint32_t f2tf32(float x) {
    uint32_t u;
    asm("cvt.rna.tf32.f32 %0, %1;" : "=r"(u) : "f"(x));
    return u;
}

__device__ __forceinline__ void mma_tf32(float* d, const uint32_t* a, const uint32_t* b) {
    asm volatile(
        "mma.sync.aligned.m16n8k8.row.col.f32.tf32.tf32.f32 "
        "{%0,%1,%2,%3}, {%4,%5,%6,%7}, {%8,%9}, {%0,%1,%2,%3};"
        : "+f"(d[0]), "+f"(d[1]), "+f"(d[2]), "+f"(d[3])
        : "r"(a[0]), "r"(a[1]), "r"(a[2]), "r"(a[3]), "r"(b[0]), "r"(b[1]));
}

template <bool ADD_BIAS>
__global__ __launch_bounds__(256, 1)
void mma_gemm_nt(const float* __restrict__ A, const float* __restrict__ Bm,
                 const float* __restrict__ bias, float* __restrict__ C,
                 int M, int N, int K,
                 long long sA, long long sB, long long sC)
{
    extern __shared__ float sm[];

    const int tid  = threadIdx.x;
    const int wid  = tid >> 5;
    const int lane = tid & 31;
    const int grp  = lane >> 2;      // 0..7
    const int quad = lane & 3;       // 0..3

    const int wm = (wid & 1) * 64;   // warp m-offset
    const int wn = (wid >> 1) * 32;  // warp n-offset

    const float* Ab = A  + (long long)blockIdx.z * sA;
    const float* Bb = Bm + (long long)blockIdx.z * sB;
    float*       Cb = C  + (long long)blockIdx.z * sC;
    const int m0 = blockIdx.y * BM;
    const int n0 = blockIdx.x * BN;
    const int S  = K / BK;

    // Loader mapping: 256 threads, 4 passes; row = tid>>3 (+32*i), col4 = (tid&7)*4
    const int lrow = tid >> 3;
    const int lj4  = (tid & 7) * 4;

    float4 rA[4], rB[4];   // register-staged global loads

    auto ldg_stage = [&](int s) {
        const int k0 = s * BK;
        #pragma unroll
        for (int i = 0; i < 4; ++i) {
            const int row = lrow + i * 32;
            rA[i] = *(const float4*)(Ab + (long long)(m0 + row) * K + k0 + lj4);
            rB[i] = *(const float4*)(Bb + (long long)(n0 + row) * K + k0 + lj4);
        }
    };

    auto sts_stage = [&](int buf) {
        float* base = sm + buf * STAGE_FLOATS;
        #pragma unroll
        for (int i = 0; i < 4; ++i) {
            const int row = lrow + i * 32;
            const int off = row * PADK + lj4;
            float4 hi, lo;
            hi.x = __uint_as_float(f2tf32(rA[i].x)); lo.x = __uint_as_float(f2tf32(rA[i].x - hi.x));
            hi.y = __uint_as_float(f2tf32(rA[i].y)); lo.y = __uint_as_float(f2tf32(rA[i].y - hi.y));
            hi.z = __uint_as_float(f2tf32(rA[i].z)); lo.z = __uint_as_float(f2tf32(rA[i].z - hi.z));
            hi.w = __uint_as_float(f2tf32(rA[i].w)); lo.w = __uint_as_float(f2tf32(rA[i].w - hi.w));
            *(float4*)(base + A_HI + off) = hi;
            *(float4*)(base + A_LO + off) = lo;
            hi.x = __uint_as_float(f2tf32(rB[i].x)); lo.x = __uint_as_float(f2tf32(rB[i].x - hi.x));
            hi.y = __uint_as_float(f2tf32(rB[i].y)); lo.y = __uint_as_float(f2tf32(rB[i].y - hi.y));
            hi.z = __uint_as_float(f2tf32(rB[i].z)); lo.z = __uint_as_float(f2tf32(rB[i].z - hi.z));
            hi.w = __uint_as_float(f2tf32(rB[i].w)); lo.w = __uint_as_float(f2tf32(rB[i].w - hi.w));
            *(float4*)(base + B_HI + off) = hi;
            *(float4*)(base + B_LO + off) = lo;
        }
    };

    float acc[4][4][4] = {};   // [mf][nf][c]

    ldg_stage(0);
    sts_stage(0);
    __syncthreads();

    for (int s = 0; s < S; ++s) {
        const int buf = s & 1;
        if (s + 1 < S) ldg_stage(s + 1);   // overlap global loads with compute

        const float* Ah = sm + buf * STAGE_FLOATS + A_HI;
        const float* Al = sm + buf * STAGE_FLOATS + A_LO;
        const float* Bh = sm + buf * STAGE_FLOATS + B_HI;
        const float* Bl = sm + buf * STAGE_FLOATS + B_LO;

        #pragma unroll
        for (int k8 = 0; k8 < BK / 8; ++k8) {
            const int kb = k8 * 8 + quad;
            uint32_t ah[4][4], al[4][4], bh[4][2], bl[4][2];
            #pragma unroll
            for (int mf = 0; mf < 4; ++mf) {
                const int r = (wm + mf * 16 + grp) * PADK + kb;
                ah[mf][0] = __float_as_uint(Ah[r]);
                ah[mf][1] = __float_as_uint(Ah[r + 8 * PADK]);
                ah[mf][2] = __float_as_uint(Ah[r + 4]);
                ah[mf][3] = __float_as_uint(Ah[r + 8 * PADK + 4]);
                al[mf][0] = __float_as_uint(Al[r]);
                al[mf][1] = __float_as_uint(Al[r + 8 * PADK]);
                al[mf][2] = __float_as_uint(Al[r + 4]);
                al[mf][3] = __float_as_uint(Al[r + 8 * PADK + 4]);
            }
            #pragma unroll
            for (int nf = 0; nf < 4; ++nf) {
                const int n = (wn + nf * 8 + grp) * PADK + kb;
                bh[nf][0] = __float_as_uint(Bh[n]);
                bh[nf][1] = __float_as_uint(Bh[n + 4]);
                bl[nf][0] = __float_as_uint(Bl[n]);
                bl[nf][1] = __float_as_uint(Bl[n + 4]);
            }
            #pragma unroll
            for (int mf = 0; mf < 4; ++mf)
                #pragma unroll
                for (int nf = 0; nf < 4; ++nf) {
                    mma_tf32(acc[mf][nf], ah[mf], bh[nf]);
                    mma_tf32(acc[mf][nf], ah[mf], bl[nf]);
                    mma_tf32(acc[mf][nf], al[mf], bh[nf]);
                }
        }
        __syncthreads();
        if (s + 1 < S) {
            sts_stage(buf ^ 1);
            __syncthreads();
        }
    }

    // Epilogue: frag (mf,nf): c0,c1 -> row grp, cols quad*2+{0,1}; c2,c3 -> row grp+8
    #pragma unroll
    for (int mf = 0; mf < 4; ++mf) {
        #pragma unroll
        for (int nf = 0; nf < 4; ++nf) {
            const int r = m0 + wm + mf * 16 + grp;
            const int c = n0 + wn + nf * 8 + quad * 2;
            float2 v0, v1;
            v0.x = acc[mf][nf][0]; v0.y = acc[mf][nf][1];
            v1.x = acc[mf][nf][2]; v1.y = acc[mf][nf][3];
            if (ADD_BIAS) {
                v0.x += bias[c]; v0.y += bias[c + 1];
                v1.x += bias[c]; v1.y += bias[c + 1];
            }
            *(float2*)(Cb + (long long)r * N + c) = v0;
            *(float2*)(Cb + (long long)(r + 8) * N + c) = v1;
        }
    }
}

// ---------------------------------------------------------------------------
// keys [B,Tk,H] -> keysT [B,H,Tk]
// ---------------------------------------------------------------------------
__global__ __launch_bounds__(256)
void transpose_keys(const float* __restrict__ in, float* __restrict__ out)
{
    __shared__ float tile[32][33];
    const int b  = blockIdx.z;
    const int t0 = blockIdx.x * 32;
    const int h0 = blockIdx.y * 32;
    const int tx = threadIdx.x;
    const int ty = threadIdx.y;
    const float* inb = in  + (long long)b * TK * HH;
    float*      outb = out + (long long)b * HH * TK;
    #pragma unroll
    for (int i = 0; i < 32; i += 8)
        tile[ty + i][tx] = inb[(long long)(t0 + ty + i) * HH + h0 + tx];
    __syncthreads();
    #pragma unroll
    for (int i = 0; i < 32; i += 8)
        outb[(long long)(h0 + ty + i) * TK + t0 + tx] = tile[tx][ty + i];
}

// ---------------------------------------------------------------------------
// In-place row softmax over TK=1024 columns.
// ---------------------------------------------------------------------------
__global__ __launch_bounds__(256)
void softmax_rows(float* __restrict__ attn)
{
    const long long row = blockIdx.x;
    float* p = attn + row * (long long)TK;
    const int tid = threadIdx.x;

    float4 v = reinterpret_cast<float4*>(p)[tid];
    __shared__ float sred[8];

    float m = fmaxf(fmaxf(v.x, v.y), fmaxf(v.z, v.w));
    #pragma unroll
    for (int o = 16; o > 0; o >>= 1)
        m = fmaxf(m, __shfl_xor_sync(0xffffffffu, m, o));
    if ((tid & 31) == 0) sred[tid >> 5] = m;
    __syncthreads();
    if (tid < 32) {
        float t = (tid < 8) ? sred[tid] : -FLT_MAX;
        #pragma unroll
        for (int o = 4; o > 0; o >>= 1)
            t = fmaxf(t, __shfl_xor_sync(0xffffffffu, t, o));
        if (tid == 0) sred[0] = t;
    }
    __syncthreads();
    const float mx = sred[0];
    __syncthreads();

    v.x = __expf(v.x - mx);
    v.y = __expf(v.y - mx);
    v.z = __expf(v.z - mx);
    v.w = __expf(v.w - mx);
    float s = v.x + v.y + v.z + v.w;
    #pragma unroll
    for (int o = 16; o > 0; o >>= 1)
        s += __shfl_xor_sync(0xffffffffu, s, o);
    if ((tid & 31) == 0) sred[tid >> 5] = s;
    __syncthreads();
    if (tid < 32) {
        float t = (tid < 8) ? sred[tid] : 0.0f;
        #pragma unroll
        for (int o = 4; o > 0; o >>= 1)
            t += __shfl_xor_sync(0xffffffffu, t, o);
        if (tid == 0) sred[0] = t;
    }
    __syncthreads();
    const float inv = 1.0f / sred[0];

    v.x *= inv; v.y *= inv; v.z *= inv; v.w *= inv;
    reinterpret_cast<float4*>(p)[tid] = v;
}

// ---------------------------------------------------------------------------
// Launch. Inputs: query [B,Tq,H], keys [B,Tk,H], W [H,H], b [H]
// Output: context [B,Tq,H] then attn_weights [B,Tq,Tk].
// ---------------------------------------------------------------------------
extern "C" void kernel_launch(void* const* d_in, const int* in_sizes, int n_in,
                              void* d_out, int out_size)
{
    const float* query = (const float*)d_in[0];
    const float* keys  = (const float*)d_in[1];
    const float* W     = (const float*)d_in[2];
    const float* bias  = (const float*)d_in[3];

    float* ctx  = (float*)d_out;                     // [B,Tq,H]
    float* attn = ctx + (long long)B_ * TQ * HH;     // [B,Tq,Tk]

    float* keysT = nullptr;
    cudaGetSymbolAddress((void**)&keysT, g_keysT);

    cudaFuncSetAttribute((const void*)mma_gemm_nt<true>,
                         cudaFuncAttributeMaxDynamicSharedMemorySize, SMEM_BYTES);
    cudaFuncSetAttribute((const void*)mma_gemm_nt<false>,
                         cudaFuncAttributeMaxDynamicSharedMemorySize, SMEM_BYTES);

    // 0) keysT = transpose(keys)
    transpose_keys<<<dim3(TK / 32, HH / 32, B_), dim3(32, 8)>>>(keys, keysT);

    // 1) q = query @ W^T + b  -> ctx scratch  [32768, 512]
    mma_gemm_nt<true><<<dim3(HH / BN, (B_ * TQ) / BM, 1), 256, SMEM_BYTES>>>(
        query, W, bias, ctx, B_ * TQ, HH, HH, 0, 0, 0);

    // 2) scores = q @ keys^T per batch -> attn [B,1024,1024]
    mma_gemm_nt<false><<<dim3(TK / BN, TQ / BM, B_), 256, SMEM_BYTES>>>(
        ctx, keys, nullptr, attn, TQ, TK, HH,
        (long long)TQ * HH, (long long)TK * HH, (long long)TQ * TK);

    // 3) softmax rows in place
    softmax_rows<<<B_ * TQ, 256>>>(attn);

    // 4) context = attn @ keysT^T per batch -> ctx
    mma_gemm_nt<false><<<dim3(HH / BN, TQ / BM, B_), 256, SMEM_BYTES>>>(
        attn, keysT, nullptr, ctx, TQ, HH, TK,
        (long long)TQ * TK, (long long)HH * TK, (long long)TQ * HH);
}

// round 5
// speedup vs baseline: 2.0152x; 1.4387x over previous
#include <cuda_runtime.h>
#include <cuda_fp16.h>
#include <float.h>
#include <stdint.h>

// Problem dims (fixed by the reference)
static constexpr int B_  = 32;
static constexpr int TQ  = 1024;
static constexpr int TK  = 1024;
static constexpr int HH  = 512;

// ---------------------------------------------------------------------------
// mma.sync fp16x3 GEMM: C[M,N] = A[M,K]*B[N,K]^T (+bias). fp32 in/out.
// CTA 128x128, K-stage 32, 8 warps each 64x32. m16n8k16 f16 MMA.
// 3-term split: D += Ahi*Bhi + Ahi*Blo + Alo*Bhi (hi/lo fp16 in smem).
// ---------------------------------------------------------------------------
static constexpr int BM = 128;
static constexpr int BN = 128;
static constexpr int BK = 32;
static constexpr int PADH2 = 18;                      // half2 words per smem row (16+2)
static constexpr int TILE_U = 128 * PADH2;            // 2304 u32 per tile
static constexpr int A_HI = 0;
static constexpr int A_LO = TILE_U;
static constexpr int B_HI = 2 * TILE_U;
static constexpr int B_LO = 3 * TILE_U;
static constexpr int STAGE_U = 4 * TILE_U;            // 9216 u32 = 36864 B
static constexpr int SMEM_BYTES = 2 * STAGE_U * 4;    // 73728 B double-buffered

__device__ float g_keysT[(size_t)B_ * HH * TK];  // 64MB scratch: keys^T [B,H,Tk]

__device__ __forceinline__ void mma_f16(float* d, const uint32_t* a, const uint32_t* b) {
    asm volatile(
        "mma.sync.aligned.m16n8k16.row.col.f32.f16.f16.f32 "
        "{%0,%1,%2,%3}, {%4,%5,%6,%7}, {%8,%9}, {%0,%1,%2,%3};"
        : "+f"(d[0]), "+f"(d[1]), "+f"(d[2]), "+f"(d[3])
        : "r"(a[0]), "r"(a[1]), "r"(a[2]), "r"(a[3]), "r"(b[0]), "r"(b[1]));
}

// split 4 floats -> (hi half2 x2, lo half2 x2) packed as uint2 each
__device__ __forceinline__ void split4(const float4& v, uint2& hi, uint2& lo) {
    __half2 h01 = __floats2half2_rn(v.x, v.y);
    __half2 h23 = __floats2half2_rn(v.z, v.w);
    __half2 l01 = __floats2half2_rn(v.x - __low2float(h01), v.y - __high2float(h01));
    __half2 l23 = __floats2half2_rn(v.z - __low2float(h23), v.w - __high2float(h23));
    hi.x = *(uint32_t*)&h01; hi.y = *(uint32_t*)&h23;
    lo.x = *(uint32_t*)&l01; lo.y = *(uint32_t*)&l23;
}

template <bool ADD_BIAS>
__global__ __launch_bounds__(256, 1)
void mma_gemm_nt(const float* __restrict__ A, const float* __restrict__ Bm,
                 const float* __restrict__ bias, float* __restrict__ C,
                 int M, int N, int K,
                 long long sA, long long sB, long long sC)
{
    extern __shared__ uint32_t sm[];

    const int tid  = threadIdx.x;
    const int wid  = tid >> 5;
    const int lane = tid & 31;
    const int grp  = lane >> 2;      // 0..7
    const int quad = lane & 3;       // 0..3

    const int wm = (wid & 1) * 64;   // warp m-offset
    const int wn = (wid >> 1) * 32;  // warp n-offset

    const float* Ab = A  + (long long)blockIdx.z * sA;
    const float* Bb = Bm + (long long)blockIdx.z * sB;
    float*       Cb = C  + (long long)blockIdx.z * sC;
    const int m0 = blockIdx.y * BM;
    const int n0 = blockIdx.x * BN;
    const int S  = K / BK;

    // Loader mapping: 256 threads, 4 passes; row = tid>>3 (+32*i), col4 = (tid&7)*4
    const int lrow = tid >> 3;
    const int lj4  = (tid & 7) * 4;           // float column
    const int lh2  = lj4 >> 1;                // half2 column (even -> 8B aligned)

    float4 rA[4], rB[4];

    auto ldg_stage = [&](int s) {
        const int k0 = s * BK;
        #pragma unroll
        for (int i = 0; i < 4; ++i) {
            const int row = lrow + i * 32;
            rA[i] = *(const float4*)(Ab + (long long)(m0 + row) * K + k0 + lj4);
            rB[i] = *(const float4*)(Bb + (long long)(n0 + row) * K + k0 + lj4);
        }
    };

    auto sts_stage = [&](int buf) {
        uint32_t* base = sm + buf * STAGE_U;
        #pragma unroll
        for (int i = 0; i < 4; ++i) {
            const int row = lrow + i * 32;
            const int off = row * PADH2 + lh2;
            uint2 hi, lo;
            split4(rA[i], hi, lo);
            *(uint2*)(base + A_HI + off) = hi;
            *(uint2*)(base + A_LO + off) = lo;
            split4(rB[i], hi, lo);
            *(uint2*)(base + B_HI + off) = hi;
            *(uint2*)(base + B_LO + off) = lo;
        }
    };

    float acc[4][4][4] = {};   // [mf][nf][c]

    ldg_stage(0);
    sts_stage(0);
    __syncthreads();

    for (int s = 0; s < S; ++s) {
        const int buf = s & 1;
        if (s + 1 < S) ldg_stage(s + 1);

        const uint32_t* Ah = sm + buf * STAGE_U + A_HI;
        const uint32_t* Al = sm + buf * STAGE_U + A_LO;
        const uint32_t* Bh = sm + buf * STAGE_U + B_HI;
        const uint32_t* Bl = sm + buf * STAGE_U + B_LO;

        #pragma unroll
        for (int k16 = 0; k16 < BK / 16; ++k16) {
            const int kq = k16 * 8 + quad;   // half2 column of first k-group
            uint32_t ah[4][4], al[4][4], bh[4][2], bl[4][2];
            #pragma unroll
            for (int mf = 0; mf < 4; ++mf) {
                const int r0 = (wm + mf * 16 + grp) * PADH2 + kq;
                ah[mf][0] = Ah[r0];
                ah[mf][1] = Ah[r0 + 8 * PADH2];
                ah[mf][2] = Ah[r0 + 4];
                ah[mf][3] = Ah[r0 + 8 * PADH2 + 4];
                al[mf][0] = Al[r0];
                al[mf][1] = Al[r0 + 8 * PADH2];
                al[mf][2] = Al[r0 + 4];
                al[mf][3] = Al[r0 + 8 * PADH2 + 4];
            }
            #pragma unroll
            for (int nf = 0; nf < 4; ++nf) {
                const int n = (wn + nf * 8 + grp) * PADH2 + kq;
                bh[nf][0] = Bh[n];
                bh[nf][1] = Bh[n + 4];
                bl[nf][0] = Bl[n];
                bl[nf][1] = Bl[n + 4];
            }
            #pragma unroll
            for (int mf = 0; mf < 4; ++mf)
                #pragma unroll
                for (int nf = 0; nf < 4; ++nf) {
                    mma_f16(acc[mf][nf], ah[mf], bh[nf]);
                    mma_f16(acc[mf][nf], ah[mf], bl[nf]);
                    mma_f16(acc[mf][nf], al[mf], bh[nf]);
                }
        }
        __syncthreads();
        if (s + 1 < S) {
            sts_stage(buf ^ 1);
            __syncthreads();
        }
    }

    // Epilogue: c0,c1 -> row grp, cols quad*2+{0,1}; c2,c3 -> row grp+8
    #pragma unroll
    for (int mf = 0; mf < 4; ++mf) {
        #pragma unroll
        for (int nf = 0; nf < 4; ++nf) {
            const int r = m0 + wm + mf * 16 + grp;
            const int c = n0 + wn + nf * 8 + quad * 2;
            float2 v0, v1;
            v0.x = acc[mf][nf][0]; v0.y = acc[mf][nf][1];
            v1.x = acc[mf][nf][2]; v1.y = acc[mf][nf][3];
            if (ADD_BIAS) {
                v0.x += bias[c]; v0.y += bias[c + 1];
                v1.x += bias[c]; v1.y += bias[c + 1];
            }
            *(float2*)(Cb + (long long)r * N + c) = v0;
            *(float2*)(Cb + (long long)(r + 8) * N + c) = v1;
        }
    }
}

// ---------------------------------------------------------------------------
// keys [B,Tk,H] -> keysT [B,H,Tk]
// ---------------------------------------------------------------------------
__global__ __launch_bounds__(256)
void transpose_keys(const float* __restrict__ in, float* __restrict__ out)
{
    __shared__ float tile[32][33];
    const int b  = blockIdx.z;
    const int t0 = blockIdx.x * 32;
    const int h0 = blockIdx.y * 32;
    const int tx = threadIdx.x;
    const int ty = threadIdx.y;
    const float* inb = in  + (long long)b * TK * HH;
    float*      outb = out + (long long)b * HH * TK;
    #pragma unroll
    for (int i = 0; i < 32; i += 8)
        tile[ty + i][tx] = inb[(long long)(t0 + ty + i) * HH + h0 + tx];
    __syncthreads();
    #pragma unroll
    for (int i = 0; i < 32; i += 8)
        outb[(long long)(h0 + ty + i) * TK + t0 + tx] = tile[tx][ty + i];
}

// ---------------------------------------------------------------------------
// In-place row softmax over TK=1024 columns.
// ---------------------------------------------------------------------------
__global__ __launch_bounds__(256)
void softmax_rows(float* __restrict__ attn)
{
    const long long row = blockIdx.x;
    float* p = attn + row * (long long)TK;
    const int tid = threadIdx.x;

    float4 v = reinterpret_cast<float4*>(p)[tid];
    __shared__ float sred[8];

    float m = fmaxf(fmaxf(v.x, v.y), fmaxf(v.z, v.w));
    #pragma unroll
    for (int o = 16; o > 0; o >>= 1)
        m = fmaxf(m, __shfl_xor_sync(0xffffffffu, m, o));
    if ((tid & 31) == 0) sred[tid >> 5] = m;
    __syncthreads();
    if (tid < 32) {
        float t = (tid < 8) ? sred[tid] : -FLT_MAX;
        #pragma unroll
        for (int o = 4; o > 0; o >>= 1)
            t = fmaxf(t, __shfl_xor_sync(0xffffffffu, t, o));
        if (tid == 0) sred[0] = t;
    }
    __syncthreads();
    const float mx = sred[0];
    __syncthreads();

    v.x = __expf(v.x - mx);
    v.y = __expf(v.y - mx);
    v.z = __expf(v.z - mx);
    v.w = __expf(v.w - mx);
    float s = v.x + v.y + v.z + v.w;
    #pragma unroll
    for (int o = 16; o > 0; o >>= 1)
        s += __shfl_xor_sync(0xffffffffu, s, o);
    if ((tid & 31) == 0) sred[tid >> 5] = s;
    __syncthreads();
    if (tid < 32) {
        float t = (tid < 8) ? sred[tid] : 0.0f;
        #pragma unroll
        for (int o = 4; o > 0; o >>= 1)
            t += __shfl_xor_sync(0xffffffffu, t, o);
        if (tid == 0) sred[0] = t;
    }
    __syncthreads();
    const float inv = 1.0f / sred[0];

    v.x *= inv; v.y *= inv; v.z *= inv; v.w *= inv;
    reinterpret_cast<float4*>(p)[tid] = v;
}

// ---------------------------------------------------------------------------
// Launch. Inputs: query [B,Tq,H], keys [B,Tk,H], W [H,H], b [H]
// Output: context [B,Tq,H] then attn_weights [B,Tq,Tk].
// ---------------------------------------------------------------------------
extern "C" void kernel_launch(void* const* d_in, const int* in_sizes, int n_in,
                              void* d_out, int out_size)
{
    const float* query = (const float*)d_in[0];
    const float* keys  = (const float*)d_in[1];
    const float* W     = (const float*)d_in[2];
    const float* bias  = (const float*)d_in[3];

    float* ctx  = (float*)d_out;                     // [B,Tq,H]
    float* attn = ctx + (long long)B_ * TQ * HH;     // [B,Tq,Tk]

    float* keysT = nullptr;
    cudaGetSymbolAddress((void**)&keysT, g_keysT);

    cudaFuncSetAttribute((const void*)mma_gemm_nt<true>,
                         cudaFuncAttributeMaxDynamicSharedMemorySize, SMEM_BYTES);
    cudaFuncSetAttribute((const void*)mma_gemm_nt<false>,
                         cudaFuncAttributeMaxDynamicSharedMemorySize, SMEM_BYTES);

    // 0) keysT = transpose(keys)
    transpose_keys<<<dim3(TK / 32, HH / 32, B_), dim3(32, 8)>>>(keys, keysT);

    // 1) q = query @ W^T + b  -> ctx scratch  [32768, 512]
    mma_gemm_nt<true><<<dim3(HH / BN, (B_ * TQ) / BM, 1), 256, SMEM_BYTES>>>(
        query, W, bias, ctx, B_ * TQ, HH, HH, 0, 0, 0);

    // 2) scores = q @ keys^T per batch -> attn [B,1024,1024]
    mma_gemm_nt<false><<<dim3(TK / BN, TQ / BM, B_), 256, SMEM_BYTES>>>(
        ctx, keys, nullptr, attn, TQ, TK, HH,
        (long long)TQ * HH, (long long)TK * HH, (long long)TQ * TK);

    // 3) softmax rows in place
    softmax_rows<<<B_ * TQ, 256>>>(attn);

    // 4) context = attn @ keysT^T per batch -> ctx
    mma_gemm_nt<false><<<dim3(HH / BN, TQ / BM, B_), 256, SMEM_BYTES>>>(
        attn, keysT, nullptr, ctx, TQ, HH, TK,
        (long long)TQ * TK, (long long)HH * TK, (long long)TQ * HH);
}

// round 6
// speedup vs baseline: 2.5060x; 1.2436x over previous
#include <cuda_runtime.h>
#include <cuda_fp16.h>
#include <float.h>
#include <stdint.h>

// Problem dims (fixed by the reference)
static constexpr int B_  = 32;
static constexpr int TQ  = 1024;
static constexpr int TK  = 1024;
static constexpr int HH  = 512;

// ---------------------------------------------------------------------------
// mma.sync fp16x3 GEMM: C[M,N] = A[M,K]*B[N,K]^T (+bias). fp32 in/out.
// CTA 128x128, K-stage 32, 8 warps each 64x32. m16n8k16 f16 MMA.
// 3-term split: D += Ahi*Bhi + Ahi*Blo + Alo*Bhi (hi/lo fp16 in smem).
// Fragment loads via ldmatrix.x4 (rows padded to 80B -> 16B-aligned, bank-safe).
// ---------------------------------------------------------------------------
static constexpr int BM = 128;
static constexpr int BN = 128;
static constexpr int BK = 32;
static constexpr int PADH2 = 20;                      // u32 (half2) per smem row: 16+4 pad (80B)
static constexpr int TILE_U = 128 * PADH2;            // 2560 u32 per tile
static constexpr int A_HI = 0;
static constexpr int A_LO = TILE_U;
static constexpr int B_HI = 2 * TILE_U;
static constexpr int B_LO = 3 * TILE_U;
static constexpr int STAGE_U = 4 * TILE_U;            // 10240 u32 = 40960 B
static constexpr int SMEM_BYTES = 2 * STAGE_U * 4;    // 81920 B double-buffered

__device__ float g_keysT[(size_t)B_ * HH * TK];  // 64MB scratch: keys^T [B,H,Tk]

__device__ __forceinline__ uint32_t smem_u32_of(const void* p) {
    uint32_t a;
    asm("{ .reg .u64 t; cvta.to.shared.u64 t, %1; cvt.u32.u64 %0, t; }"
        : "=r"(a) : "l"(p));
    return a;
}

__device__ __forceinline__ void mma_f16(float* d, const uint32_t* a, const uint32_t* b) {
    asm volatile(
        "mma.sync.aligned.m16n8k16.row.col.f32.f16.f16.f32 "
        "{%0,%1,%2,%3}, {%4,%5,%6,%7}, {%8,%9}, {%0,%1,%2,%3};"
        : "+f"(d[0]), "+f"(d[1]), "+f"(d[2]), "+f"(d[3])
        : "r"(a[0]), "r"(a[1]), "r"(a[2]), "r"(a[3]), "r"(b[0]), "r"(b[1]));
}

__device__ __forceinline__ void ldsm_x4(uint32_t* r, uint32_t saddr) {
    asm volatile("ldmatrix.sync.aligned.m8n8.x4.shared.b16 {%0,%1,%2,%3}, [%4];"
                 : "=r"(r[0]), "=r"(r[1]), "=r"(r[2]), "=r"(r[3]) : "r"(saddr));
}

// split 4 floats -> (hi half2 x2, lo half2 x2) packed as uint2 each
__device__ __forceinline__ void split4(const float4& v, uint2& hi, uint2& lo) {
    __half2 h01 = __floats2half2_rn(v.x, v.y);
    __half2 h23 = __floats2half2_rn(v.z, v.w);
    __half2 l01 = __floats2half2_rn(v.x - __low2float(h01), v.y - __high2float(h01));
    __half2 l23 = __floats2half2_rn(v.z - __low2float(h23), v.w - __high2float(h23));
    hi.x = *(uint32_t*)&h01; hi.y = *(uint32_t*)&h23;
    lo.x = *(uint32_t*)&l01; lo.y = *(uint32_t*)&l23;
}

template <bool ADD_BIAS>
__global__ __launch_bounds__(256, 1)
void mma_gemm_nt(const float* __restrict__ A, const float* __restrict__ Bm,
                 const float* __restrict__ bias, float* __restrict__ C,
                 int M, int N, int K,
                 long long sA, long long sB, long long sC)
{
    extern __shared__ uint32_t sm[];
    const uint32_t smem_base = smem_u32_of(sm);

    const int tid  = threadIdx.x;
    const int wid  = tid >> 5;
    const int lane = tid & 31;
    const int grp  = lane >> 2;
    const int quad = lane & 3;

    const int wm = (wid & 1) * 64;   // warp m-offset
    const int wn = (wid >> 1) * 32;  // warp n-offset

    const float* Ab = A  + (long long)blockIdx.z * sA;
    const float* Bb = Bm + (long long)blockIdx.z * sB;
    float*       Cb = C  + (long long)blockIdx.z * sC;
    const int m0 = blockIdx.y * BM;
    const int n0 = blockIdx.x * BN;
    const int S  = K / BK;

    // ldmatrix lane -> address components
    // A (.x4): mat0 rows 0-7 k0 | mat1 rows 8-15 k0 | mat2 rows 0-7 k8 | mat3 rows 8-15 k8
    const int a_row = (lane & 15);                 // lanes 0-15 rows 0-15, repeat for 16-31
    const int a_k   = (lane & 16) ? 4 : 0;         // half2 col offset (fp16 +8)
    // B (.x4): mat0 (nf0,k0) | mat1 (nf0,k8) | mat2 (nf1,k0) | mat3 (nf1,k8)
    const int b_row = (lane & 7) + ((lane & 16) ? 8 : 0);
    const int b_k   = (lane & 8) ? 4 : 0;

    // byte offsets within a stage for each ldmatrix base
    uint32_t aoff[4], boff[2];
    #pragma unroll
    for (int mf = 0; mf < 4; ++mf)
        aoff[mf] = (uint32_t)((A_HI + (wm + mf * 16 + a_row) * PADH2 + a_k) * 4);
    #pragma unroll
    for (int np = 0; np < 2; ++np)
        boff[np] = (uint32_t)((B_HI + (wn + np * 16 + b_row) * PADH2 + b_k) * 4);
    const uint32_t LO_A = (uint32_t)(TILE_U * 4);   // A_LO - A_HI in bytes
    const uint32_t LO_B = (uint32_t)(TILE_U * 4);   // B_LO - B_HI in bytes

    // Loader mapping: 256 threads, 4 passes; row = tid>>3 (+32*i), col4 = (tid&7)*4
    const int lrow = tid >> 3;
    const int lj4  = (tid & 7) * 4;
    const int lh2  = lj4 >> 1;

    float4 rA[4], rB[4];

    auto ldg_stage = [&](int s) {
        const int k0 = s * BK;
        #pragma unroll
        for (int i = 0; i < 4; ++i) {
            const int row = lrow + i * 32;
            rA[i] = *(const float4*)(Ab + (long long)(m0 + row) * K + k0 + lj4);
            rB[i] = *(const float4*)(Bb + (long long)(n0 + row) * K + k0 + lj4);
        }
    };

    auto sts_stage = [&](int buf) {
        uint32_t* base = sm + buf * STAGE_U;
        #pragma unroll
        for (int i = 0; i < 4; ++i) {
            const int row = lrow + i * 32;
            const int off = row * PADH2 + lh2;
            uint2 hi, lo;
            split4(rA[i], hi, lo);
            *(uint2*)(base + A_HI + off) = hi;
            *(uint2*)(base + A_LO + off) = lo;
            split4(rB[i], hi, lo);
            *(uint2*)(base + B_HI + off) = hi;
            *(uint2*)(base + B_LO + off) = lo;
        }
    };

    float acc[4][4][4] = {};   // [mf][nf][c]

    ldg_stage(0);
    sts_stage(0);
    __syncthreads();

    for (int s = 0; s < S; ++s) {
        const int buf = s & 1;
        if (s + 1 < S) ldg_stage(s + 1);

        const uint32_t sb = smem_base + (uint32_t)(buf * STAGE_U * 4);

        #pragma unroll
        for (int k16 = 0; k16 < BK / 16; ++k16) {
            const uint32_t kb = (uint32_t)(k16 * 32);   // 8 half2 = 32 bytes
            uint32_t ah[4][4], al[4][4];
            uint32_t bhv[2][4], blv[2][4];
            #pragma unroll
            for (int mf = 0; mf < 4; ++mf) {
                ldsm_x4(ah[mf], sb + aoff[mf] + kb);
                ldsm_x4(al[mf], sb + aoff[mf] + LO_A + kb);
            }
            #pragma unroll
            for (int np = 0; np < 2; ++np) {
                ldsm_x4(bhv[np], sb + boff[np] + kb);
                ldsm_x4(blv[np], sb + boff[np] + LO_B + kb);
            }
            #pragma unroll
            for (int mf = 0; mf < 4; ++mf)
                #pragma unroll
                for (int nf = 0; nf < 4; ++nf) {
                    const int np = nf >> 1;
                    const int rp = (nf & 1) * 2;
                    mma_f16(acc[mf][nf], ah[mf], &bhv[np][rp]);
                    mma_f16(acc[mf][nf], ah[mf], &blv[np][rp]);
                    mma_f16(acc[mf][nf], al[mf], &bhv[np][rp]);
                }
        }
        __syncthreads();
        if (s + 1 < S) {
            sts_stage(buf ^ 1);
            __syncthreads();
        }
    }

    // Epilogue: c0,c1 -> row grp, cols quad*2+{0,1}; c2,c3 -> row grp+8
    #pragma unroll
    for (int mf = 0; mf < 4; ++mf) {
        #pragma unroll
        for (int nf = 0; nf < 4; ++nf) {
            const int r = m0 + wm + mf * 16 + grp;
            const int c = n0 + wn + nf * 8 + quad * 2;
            float2 v0, v1;
            v0.x = acc[mf][nf][0]; v0.y = acc[mf][nf][1];
            v1.x = acc[mf][nf][2]; v1.y = acc[mf][nf][3];
            if (ADD_BIAS) {
                v0.x += bias[c]; v0.y += bias[c + 1];
                v1.x += bias[c]; v1.y += bias[c + 1];
            }
            *(float2*)(Cb + (long long)r * N + c) = v0;
            *(float2*)(Cb + (long long)(r + 8) * N + c) = v1;
        }
    }
}

// ---------------------------------------------------------------------------
// keys [B,Tk,H] -> keysT [B,H,Tk]
// ---------------------------------------------------------------------------
__global__ __launch_bounds__(256)
void transpose_keys(const float* __restrict__ in, float* __restrict__ out)
{
    __shared__ float tile[32][33];
    const int b  = blockIdx.z;
    const int t0 = blockIdx.x * 32;
    const int h0 = blockIdx.y * 32;
    const int tx = threadIdx.x;
    const int ty = threadIdx.y;
    const float* inb = in  + (long long)b * TK * HH;
    float*      outb = out + (long long)b * HH * TK;
    #pragma unroll
    for (int i = 0; i < 32; i += 8)
        tile[ty + i][tx] = inb[(long long)(t0 + ty + i) * HH + h0 + tx];
    __syncthreads();
    #pragma unroll
    for (int i = 0; i < 32; i += 8)
        outb[(long long)(h0 + ty + i) * TK + t0 + tx] = tile[tx][ty + i];
}

// ---------------------------------------------------------------------------
// In-place row softmax over TK=1024 columns.
// ---------------------------------------------------------------------------
__global__ __launch_bounds__(256)
void softmax_rows(float* __restrict__ attn)
{
    const long long row = blockIdx.x;
    float* p = attn + row * (long long)TK;
    const int tid = threadIdx.x;

    float4 v = reinterpret_cast<float4*>(p)[tid];
    __shared__ float sred[8];

    float m = fmaxf(fmaxf(v.x, v.y), fmaxf(v.z, v.w));
    #pragma unroll
    for (int o = 16; o > 0; o >>= 1)
        m = fmaxf(m, __shfl_xor_sync(0xffffffffu, m, o));
    if ((tid & 31) == 0) sred[tid >> 5] = m;
    __syncthreads();
    if (tid < 32) {
        float t = (tid < 8) ? sred[tid] : -FLT_MAX;
        #pragma unroll
        for (int o = 4; o > 0; o >>= 1)
            t = fmaxf(t, __shfl_xor_sync(0xffffffffu, t, o));
        if (tid == 0) sred[0] = t;
    }
    __syncthreads();
    const float mx = sred[0];
    __syncthreads();

    v.x = __expf(v.x - mx);
    v.y = __expf(v.y - mx);
    v.z = __expf(v.z - mx);
    v.w = __expf(v.w - mx);
    float s = v.x + v.y + v.z + v.w;
    #pragma unroll
    for (int o = 16; o > 0; o >>= 1)
        s += __shfl_xor_sync(0xffffffffu, s, o);
    if ((tid & 31) == 0) sred[tid >> 5] = s;
    __syncthreads();
    if (tid < 32) {
        float t = (tid < 8) ? sred[tid] : 0.0f;
        #pragma unroll
        for (int o = 4; o > 0; o >>= 1)
            t += __shfl_xor_sync(0xffffffffu, t, o);
        if (tid == 0) sred[0] = t;
    }
    __syncthreads();
    const float inv = 1.0f / sred[0];

    v.x *= inv; v.y *= inv; v.z *= inv; v.w *= inv;
    reinterpret_cast<float4*>(p)[tid] = v;
}

// ---------------------------------------------------------------------------
// Launch. Inputs: query [B,Tq,H], keys [B,Tk,H], W [H,H], b [H]
// Output: context [B,Tq,H] then attn_weights [B,Tq,Tk].
// ---------------------------------------------------------------------------
extern "C" void kernel_launch(void* const* d_in, const int* in_sizes, int n_in,
                              void* d_out, int out_size)
{
    const float* query = (const float*)d_in[0];
    const float* keys  = (const float*)d_in[1];
    const float* W     = (const float*)d_in[2];
    const float* bias  = (const float*)d_in[3];

    float* ctx  = (float*)d_out;                     // [B,Tq,H]
    float* attn = ctx + (long long)B_ * TQ * HH;     // [B,Tq,Tk]

    float* keysT = nullptr;
    cudaGetSymbolAddress((void**)&keysT, g_keysT);

    cudaFuncSetAttribute((const void*)mma_gemm_nt<true>,
                         cudaFuncAttributeMaxDynamicSharedMemorySize, SMEM_BYTES);
    cudaFuncSetAttribute((const void*)mma_gemm_nt<false>,
                         cudaFuncAttributeMaxDynamicSharedMemorySize, SMEM_BYTES);

    // 0) keysT = transpose(keys)
    transpose_keys<<<dim3(TK / 32, HH / 32, B_), dim3(32, 8)>>>(keys, keysT);

    // 1) q = query @ W^T + b  -> ctx scratch  [32768, 512]
    mma_gemm_nt<true><<<dim3(HH / BN, (B_ * TQ) / BM, 1), 256, SMEM_BYTES>>>(
        query, W, bias, ctx, B_ * TQ, HH, HH, 0, 0, 0);

    // 2) scores = q @ keys^T per batch -> attn [B,1024,1024]
    mma_gemm_nt<false><<<dim3(TK / BN, TQ / BM, B_), 256, SMEM_BYTES>>>(
        ctx, keys, nullptr, attn, TQ, TK, HH,
        (long long)TQ * HH, (long long)TK * HH, (long long)TQ * TK);

    // 3) softmax rows in place
    softmax_rows<<<B_ * TQ, 256>>>(attn);

    // 4) context = attn @ keysT^T per batch -> ctx
    mma_gemm_nt<false><<<dim3(HH / BN, TQ / BM, B_), 256, SMEM_BYTES>>>(
        attn, keysT, nullptr, ctx, TQ, HH, TK,
        (long long)TQ * TK, (long long)HH * TK, (long long)TQ * HH);
}

// round 7
// speedup vs baseline: 2.5693x; 1.0253x over previous
#include <cuda_runtime.h>
#include <cuda_fp16.h>
#include <float.h>
#include <stdint.h>

// Problem dims (fixed by the reference)
static constexpr int B_  = 32;
static constexpr int TQ  = 1024;
static constexpr int TK  = 1024;
static constexpr int HH  = 512;

// ---------------------------------------------------------------------------
// fp16x3 GEMM, operands pre-split to hi/lo fp16 in gmem.
// C[M,N] = A[M,K]*B[N,K]^T (+bias). CTA 128x128, BK=32, 3-stage cp.async.
// smem row (per tile row): [hi 32h | lo 32h] = 128B, XOR-swizzled by row&7.
// ---------------------------------------------------------------------------
static constexpr int BM = 128;
static constexpr int BN = 128;
static constexpr int BK = 32;
static constexpr int STAGES = 3;
static constexpr int TILE_BYTES  = 128 * 128;          // 16KB per operand tile
static constexpr int B_OFF       = TILE_BYTES;         // B tile offset in stage
static constexpr int STAGE_BYTES = 2 * TILE_BYTES;     // 32KB
static constexpr int SMEM_BYTES  = STAGES * STAGE_BYTES;  // 96KB

// ---- pre-split fp16 scratch (device globals; no allocations) ----
__device__ __half g_qry_hi [(size_t)B_ * TQ * HH];
__device__ __half g_qry_lo [(size_t)B_ * TQ * HH];
__device__ __half g_W_hi   [(size_t)HH * HH];
__device__ __half g_W_lo   [(size_t)HH * HH];
__device__ __half g_keys_hi[(size_t)B_ * TK * HH];
__device__ __half g_keys_lo[(size_t)B_ * TK * HH];
__device__ __half g_keysT_hi[(size_t)B_ * HH * TK];
__device__ __half g_keysT_lo[(size_t)B_ * HH * TK];
__device__ __half g_q_hi   [(size_t)B_ * TQ * HH];
__device__ __half g_q_lo   [(size_t)B_ * TQ * HH];
__device__ __half g_attn_hi[(size_t)B_ * TQ * TK];
__device__ __half g_attn_lo[(size_t)B_ * TQ * TK];

__device__ __forceinline__ uint32_t smem_u32_of(const void* p) {
    uint32_t a;
    asm("{ .reg .u64 t; cvta.to.shared.u64 t, %1; cvt.u32.u64 %0, t; }"
        : "=r"(a) : "l"(p));
    return a;
}

__device__ __forceinline__ void cp_async16(uint32_t dst, const void* src) {
    asm volatile("cp.async.cg.shared.global [%0], [%1], 16;"
                 :: "r"(dst), "l"(src) : "memory");
}
#define CP_COMMIT() asm volatile("cp.async.commit_group;" ::: "memory")
#define CP_WAIT(n)  asm volatile("cp.async.wait_group %0;" :: "n"(n) : "memory")

__device__ __forceinline__ void mma_f16(float* d, const uint32_t* a, const uint32_t* b) {
    asm volatile(
        "mma.sync.aligned.m16n8k16.row.col.f32.f16.f16.f32 "
        "{%0,%1,%2,%3}, {%4,%5,%6,%7}, {%8,%9}, {%0,%1,%2,%3};"
        : "+f"(d[0]), "+f"(d[1]), "+f"(d[2]), "+f"(d[3])
        : "r"(a[0]), "r"(a[1]), "r"(a[2]), "r"(a[3]), "r"(b[0]), "r"(b[1]));
}

__device__ __forceinline__ void ldsm_x4(uint32_t* r, uint32_t saddr) {
    asm volatile("ldmatrix.sync.aligned.m8n8.x4.shared.b16 {%0,%1,%2,%3}, [%4];"
                 : "=r"(r[0]), "=r"(r[1]), "=r"(r[2]), "=r"(r[3]) : "r"(saddr));
}

// ---------------------------------------------------------------------------
// GEMM kernel. OUT_HILO: write hi/lo fp16 (with bias) instead of fp32.
// ---------------------------------------------------------------------------
template <bool ADD_BIAS, bool OUT_HILO>
__global__ __launch_bounds__(256, 1)
void gemm_hilo(const __half* __restrict__ Ahi, const __half* __restrict__ Alo,
               const __half* __restrict__ Bhi, const __half* __restrict__ Blo,
               const float* __restrict__ bias,
               float* __restrict__ Cf, __half* __restrict__ Chi, __half* __restrict__ Clo,
               int M, int N, int K,
               long long sA, long long sB, long long sC)
{
    extern __shared__ char sm[];
    const uint32_t smem_base = smem_u32_of(sm);

    const int tid  = threadIdx.x;
    const int wid  = tid >> 5;
    const int lane = tid & 31;
    const int grp  = lane >> 2;
    const int quad = lane & 3;

    const int wm = (wid & 1) * 64;
    const int wn = (wid >> 1) * 32;

    const __half* Ah_g = Ahi + (long long)blockIdx.z * sA;
    const __half* Al_g = Alo + (long long)blockIdx.z * sA;
    const __half* Bh_g = Bhi + (long long)blockIdx.z * sB;
    const __half* Bl_g = Blo + (long long)blockIdx.z * sB;
    const int m0 = blockIdx.y * BM;
    const int n0 = blockIdx.x * BN;
    const int S  = K / BK;

    // ---- cp.async loader: per stage, 4 A chunks + 4 B chunks per thread ----
    // chunk id -> row = id>>3, c = id&7 ; c<4: hi halves [c*8..), c>=4: lo
    const int lrow = tid >> 1;              // base rows: 2 chunks/row per pass? No:
    // simpler: id = tid + i*256 over 1024 chunks
    auto load_stage = [&](int s, int buf) {
        const int k0 = s * BK;
        const uint32_t sb = smem_base + (uint32_t)(buf * STAGE_BYTES);
        #pragma unroll
        for (int i = 0; i < 4; ++i) {
            const int id  = tid + i * 256;
            const int row = id >> 3;
            const int c   = id & 7;
            const __half* src = ((c < 4) ? Ah_g : Al_g)
                              + (long long)(m0 + row) * K + k0 + (c & 3) * 8;
            cp_async16(sb + (uint32_t)(row * 128 + ((c ^ (row & 7)) << 4)), src);
        }
        #pragma unroll
        for (int i = 0; i < 4; ++i) {
            const int id  = tid + i * 256;
            const int row = id >> 3;
            const int c   = id & 7;
            const __half* src = ((c < 4) ? Bh_g : Bl_g)
                              + (long long)(n0 + row) * K + k0 + (c & 3) * 8;
            cp_async16(sb + (uint32_t)(B_OFF + row * 128 + ((c ^ (row & 7)) << 4)), src);
        }
    };

    // ---- ldmatrix lane addressing (same fragment order as proven R6) ----
    // A: lanes 0-15 -> rows 0-15 @k0 (mats 0,1); lanes 16-31 -> rows 0-15 @k8 (mats 2,3)
    const int a_rowl = lane & 15;
    const int a_cb   = (lane >> 4) & 1;    // col unit (16B): 0 for k0, 1 for k8
    // B: lanes 0-7 rows0-7@k0 | 8-15 rows0-7@k8 | 16-23 rows8-15@k0 | 24-31 rows8-15@k8
    const int b_rowl = (lane & 7) + ((lane & 16) ? 8 : 0);
    const int b_cb   = (lane >> 3) & 1;

    uint32_t a_ro[4]; int a_rm[4];
    #pragma unroll
    for (int mf = 0; mf < 4; ++mf) {
        const int row = wm + mf * 16 + a_rowl;
        a_ro[mf] = (uint32_t)(row * 128);
        a_rm[mf] = row & 7;
    }
    uint32_t b_ro[2]; int b_rm[2];
    #pragma unroll
    for (int np = 0; np < 2; ++np) {
        const int row = wn + np * 16 + b_rowl;
        b_ro[np] = (uint32_t)(B_OFF + row * 128);
        b_rm[np] = row & 7;
    }

    float acc[4][4][4] = {};

    // ---- prologue ----
    load_stage(0, 0); CP_COMMIT();
    if (S > 1) { load_stage(1, 1); CP_COMMIT(); }
    CP_WAIT(1);
    __syncthreads();

    for (int s = 0; s < S; ++s) {
        const int buf = s % 3;
        const uint32_t sb = smem_base + (uint32_t)(buf * STAGE_BYTES);

        #pragma unroll
        for (int k16 = 0; k16 < BK / 16; ++k16) {
            uint32_t ah[4][4], al[4][4], bhv[2][4], blv[2][4];
            #pragma unroll
            for (int mf = 0; mf < 4; ++mf) {
                const int ch = a_cb + 2 * k16;
                ldsm_x4(ah[mf], sb + a_ro[mf] + (uint32_t)(((ch)     ^ a_rm[mf]) << 4));
                ldsm_x4(al[mf], sb + a_ro[mf] + (uint32_t)(((ch + 4) ^ a_rm[mf]) << 4));
            }
            #pragma unroll
            for (int np = 0; np < 2; ++np) {
                const int ch = b_cb + 2 * k16;
                ldsm_x4(bhv[np], sb + b_ro[np] + (uint32_t)(((ch)     ^ b_rm[np]) << 4));
                ldsm_x4(blv[np], sb + b_ro[np] + (uint32_t)(((ch + 4) ^ b_rm[np]) << 4));
            }
            #pragma unroll
            for (int mf = 0; mf < 4; ++mf)
                #pragma unroll
                for (int nf = 0; nf < 4; ++nf) {
                    const int np = nf >> 1;
                    const int rp = (nf & 1) * 2;
                    mma_f16(acc[mf][nf], ah[mf], &bhv[np][rp]);
                    mma_f16(acc[mf][nf], ah[mf], &blv[np][rp]);
                    mma_f16(acc[mf][nf], al[mf], &bhv[np][rp]);
                }
        }

        if (s + 2 < S) { load_stage(s + 2, (s + 2) % 3); CP_COMMIT(); CP_WAIT(1); }
        else           { CP_WAIT(0); }
        __syncthreads();
    }

    // ---- epilogue ----
    #pragma unroll
    for (int mf = 0; mf < 4; ++mf) {
        #pragma unroll
        for (int nf = 0; nf < 4; ++nf) {
            const int r = m0 + wm + mf * 16 + grp;
            const int c = n0 + wn + nf * 8 + quad * 2;
            float v0 = acc[mf][nf][0], v1 = acc[mf][nf][1];
            float v2 = acc[mf][nf][2], v3 = acc[mf][nf][3];
            if (ADD_BIAS) {
                const float b0 = bias[c], b1 = bias[c + 1];
                v0 += b0; v1 += b1; v2 += b0; v3 += b1;
            }
            if (OUT_HILO) {
                const long long o0 = (long long)r * N + c + (long long)blockIdx.z * sC;
                const long long o1 = (long long)(r + 8) * N + c + (long long)blockIdx.z * sC;
                __half2 h0 = __floats2half2_rn(v0, v1);
                __half2 l0 = __floats2half2_rn(v0 - __low2float(h0), v1 - __high2float(h0));
                __half2 h1 = __floats2half2_rn(v2, v3);
                __half2 l1 = __floats2half2_rn(v2 - __low2float(h1), v3 - __high2float(h1));
                *(__half2*)(Chi + o0) = h0;
                *(__half2*)(Clo + o0) = l0;
                *(__half2*)(Chi + o1) = h1;
                *(__half2*)(Clo + o1) = l1;
            } else {
                float* Cb = Cf + (long long)blockIdx.z * sC;
                float2 w0; w0.x = v0; w0.y = v1;
                float2 w1; w1.x = v2; w1.y = v3;
                *(float2*)(Cb + (long long)r * N + c) = w0;
                *(float2*)(Cb + (long long)(r + 8) * N + c) = w1;
            }
        }
    }
}

// ---------------------------------------------------------------------------
// Elementwise fp32 -> hi/lo fp16 split (float4 per thread).
// ---------------------------------------------------------------------------
__global__ __launch_bounds__(256)
void split_f32(const float* __restrict__ in, __half* __restrict__ hi,
               __half* __restrict__ lo, long long n4)
{
    const long long i = (long long)blockIdx.x * 256 + threadIdx.x;
    if (i >= n4) return;
    float4 v = ((const float4*)in)[i];
    __half2 h01 = __floats2half2_rn(v.x, v.y);
    __half2 h23 = __floats2half2_rn(v.z, v.w);
    __half2 l01 = __floats2half2_rn(v.x - __low2float(h01), v.y - __high2float(h01));
    __half2 l23 = __floats2half2_rn(v.z - __low2float(h23), v.w - __high2float(h23));
    ((__half2*)hi)[i * 2]     = h01;
    ((__half2*)hi)[i * 2 + 1] = h23;
    ((__half2*)lo)[i * 2]     = l01;
    ((__half2*)lo)[i * 2 + 1] = l23;
}

// ---------------------------------------------------------------------------
// keys -> keys hi/lo [B,Tk,H]  +  keysT hi/lo [B,H,Tk]
// ---------------------------------------------------------------------------
__global__ __launch_bounds__(256)
void split_keys_all(const float* __restrict__ keys,
                    __half* __restrict__ khi, __half* __restrict__ klo,
                    __half* __restrict__ kThi, __half* __restrict__ kTlo)
{
    __shared__ float tile[32][33];
    const int b  = blockIdx.z;
    const int t0 = blockIdx.x * 32;
    const int h0 = blockIdx.y * 32;
    const int tx = threadIdx.x;
    const int ty = threadIdx.y;
    const float* inb = keys + (long long)b * TK * HH;
    __half* khb  = khi  + (long long)b * TK * HH;
    __half* klb  = klo  + (long long)b * TK * HH;
    __half* kThb = kThi + (long long)b * HH * TK;
    __half* kTlb = kTlo + (long long)b * HH * TK;

    #pragma unroll
    for (int i = 0; i < 32; i += 8) {
        float v = inb[(long long)(t0 + ty + i) * HH + h0 + tx];
        tile[ty + i][tx] = v;
        __half h = __float2half_rn(v);
        khb[(long long)(t0 + ty + i) * HH + h0 + tx] = h;
        klb[(long long)(t0 + ty + i) * HH + h0 + tx] = __float2half_rn(v - __half2float(h));
    }
    __syncthreads();
    #pragma unroll
    for (int i = 0; i < 32; i += 8) {
        float v = tile[tx][ty + i];
        __half h = __float2half_rn(v);
        kThb[(long long)(h0 + ty + i) * TK + t0 + tx] = h;
        kTlb[(long long)(h0 + ty + i) * TK + t0 + tx] = __float2half_rn(v - __half2float(h));
    }
}

// ---------------------------------------------------------------------------
// In-place row softmax over TK=1024; also emits hi/lo fp16 copy.
// ---------------------------------------------------------------------------
__global__ __launch_bounds__(256)
void softmax_rows(float* __restrict__ attn, __half* __restrict__ ahi,
                  __half* __restrict__ alo)
{
    const long long row = blockIdx.x;
    float* p = attn + row * (long long)TK;
    const int tid = threadIdx.x;

    float4 v = reinterpret_cast<float4*>(p)[tid];
    __shared__ float sred[8];

    float m = fmaxf(fmaxf(v.x, v.y), fmaxf(v.z, v.w));
    #pragma unroll
    for (int o = 16; o > 0; o >>= 1)
        m = fmaxf(m, __shfl_xor_sync(0xffffffffu, m, o));
    if ((tid & 31) == 0) sred[tid >> 5] = m;
    __syncthreads();
    if (tid < 32) {
        float t = (tid < 8) ? sred[tid] : -FLT_MAX;
        #pragma unroll
        for (int o = 4; o > 0; o >>= 1)
            t = fmaxf(t, __shfl_xor_sync(0xffffffffu, t, o));
        if (tid == 0) sred[0] = t;
    }
    __syncthreads();
    const float mx = sred[0];
    __syncthreads();

    v.x = __expf(v.x - mx);
    v.y = __expf(v.y - mx);
    v.z = __expf(v.z - mx);
    v.w = __expf(v.w - mx);
    float s = v.x + v.y + v.z + v.w;
    #pragma unroll
    for (int o = 16; o > 0; o >>= 1)
        s += __shfl_xor_sync(0xffffffffu, s, o);
    if ((tid & 31) == 0) sred[tid >> 5] = s;
    __syncthreads();
    if (tid < 32) {
        float t = (tid < 8) ? sred[tid] : 0.0f;
        #pragma unroll
        for (int o = 4; o > 0; o >>= 1)
            t += __shfl_xor_sync(0xffffffffu, t, o);
        if (tid == 0) sred[0] = t;
    }
    __syncthreads();
    const float inv = 1.0f / sred[0];

    v.x *= inv; v.y *= inv; v.z *= inv; v.w *= inv;
    reinterpret_cast<float4*>(p)[tid] = v;

    __half2 h01 = __floats2half2_rn(v.x, v.y);
    __half2 h23 = __floats2half2_rn(v.z, v.w);
    __half2 l01 = __floats2half2_rn(v.x - __low2float(h01), v.y - __high2float(h01));
    __half2 l23 = __floats2half2_rn(v.z - __low2float(h23), v.w - __high2float(h23));
    __half2* hp = (__half2*)(ahi + row * (long long)TK) + tid * 2;
    __half2* lp = (__half2*)(alo + row * (long long)TK) + tid * 2;
    hp[0] = h01; hp[1] = h23;
    lp[0] = l01; lp[1] = l23;
}

// ---------------------------------------------------------------------------
// Launch. Inputs: query [B,Tq,H], keys [B,Tk,H], W [H,H], b [H]
// Output: context [B,Tq,H] then attn_weights [B,Tq,Tk].
// ---------------------------------------------------------------------------
extern "C" void kernel_launch(void* const* d_in, const int* in_sizes, int n_in,
                              void* d_out, int out_size)
{
    const float* query = (const float*)d_in[0];
    const float* keys  = (const float*)d_in[1];
    const float* W     = (const float*)d_in[2];
    const float* bias  = (const float*)d_in[3];

    float* ctx  = (float*)d_out;                     // [B,Tq,H]
    float* attn = ctx + (long long)B_ * TQ * HH;     // [B,Tq,Tk]

    __half *qry_hi, *qry_lo, *W_hi, *W_lo, *keys_hi, *keys_lo;
    __half *keysT_hi, *keysT_lo, *q_hi, *q_lo, *attn_hi, *attn_lo;
    cudaGetSymbolAddress((void**)&qry_hi,  g_qry_hi);
    cudaGetSymbolAddress((void**)&qry_lo,  g_qry_lo);
    cudaGetSymbolAddress((void**)&W_hi,    g_W_hi);
    cudaGetSymbolAddress((void**)&W_lo,    g_W_lo);
    cudaGetSymbolAddress((void**)&keys_hi, g_keys_hi);
    cudaGetSymbolAddress((void**)&keys_lo, g_keys_lo);
    cudaGetSymbolAddress((void**)&keysT_hi, g_keysT_hi);
    cudaGetSymbolAddress((void**)&keysT_lo, g_keysT_lo);
    cudaGetSymbolAddress((void**)&q_hi,    g_q_hi);
    cudaGetSymbolAddress((void**)&q_lo,    g_q_lo);
    cudaGetSymbolAddress((void**)&attn_hi, g_attn_hi);
    cudaGetSymbolAddress((void**)&attn_lo, g_attn_lo);

    cudaFuncSetAttribute((const void*)gemm_hilo<true, true>,
                         cudaFuncAttributeMaxDynamicSharedMemorySize, SMEM_BYTES);
    cudaFuncSetAttribute((const void*)gemm_hilo<false, false>,
                         cudaFuncAttributeMaxDynamicSharedMemorySize, SMEM_BYTES);

    // 0) splits
    {
        long long n4q = (long long)B_ * TQ * HH / 4;
        split_f32<<<(unsigned)((n4q + 255) / 256), 256>>>(query, qry_hi, qry_lo, n4q);
        long long n4w = (long long)HH * HH / 4;
        split_f32<<<(unsigned)((n4w + 255) / 256), 256>>>(W, W_hi, W_lo, n4w);
        split_keys_all<<<dim3(TK / 32, HH / 32, B_), dim3(32, 8)>>>(
            keys, keys_hi, keys_lo, keysT_hi, keysT_lo);
    }

    // 1) q = query @ W^T + b -> q_hi/q_lo fp16
    gemm_hilo<true, true><<<dim3(HH / BN, (B_ * TQ) / BM, 1), 256, SMEM_BYTES>>>(
        qry_hi, qry_lo, W_hi, W_lo, bias,
        nullptr, q_hi, q_lo,
        B_ * TQ, HH, HH, 0, 0, 0);

    // 2) scores = q @ keys^T per batch -> attn fp32
    gemm_hilo<false, false><<<dim3(TK / BN, TQ / BM, B_), 256, SMEM_BYTES>>>(
        q_hi, q_lo, keys_hi, keys_lo, nullptr,
        attn, nullptr, nullptr,
        TQ, TK, HH,
        (long long)TQ * HH, (long long)TK * HH, (long long)TQ * TK);

    // 3) softmax rows in place + emit hi/lo fp16
    softmax_rows<<<B_ * TQ, 256>>>(attn, attn_hi, attn_lo);

    // 4) context = attn @ keysT^T per batch -> ctx fp32
    gemm_hilo<false, false><<<dim3(HH / BN, TQ / BM, B_), 256, SMEM_BYTES>>>(
        attn_hi, attn_lo, keysT_hi, keysT_lo, nullptr,
        ctx, nullptr, nullptr,
        TQ, HH, TK,
        (long long)TQ * TK, (long long)HH * TK, (long long)TQ * HH);
}

// round 8
// speedup vs baseline: 2.6461x; 1.0299x over previous
#include <cuda_runtime.h>
#include <cuda_fp16.h>
#include <float.h>
#include <stdint.h>

// Problem dims (fixed by the reference)
static constexpr int B_  = 32;
static constexpr int TQ  = 1024;
static constexpr int TK  = 1024;
static constexpr int HH  = 512;

// ---------------------------------------------------------------------------
// fp16x3 GEMM, operands pre-split to hi/lo fp16 in gmem.
// C[M,N] = A[M,K]*B[N,K]^T (+bias). CTA 128x128, BK=32, 3-stage cp.async.
// smem row (per tile row): [hi 32h | lo 32h] = 128B, XOR-swizzled by row&7.
// 2 CTAs/SM (launch_bounds 256,2) to overlap barriers/prologues.
// ---------------------------------------------------------------------------
static constexpr int BM = 128;
static constexpr int BN = 128;
static constexpr int BK = 32;
static constexpr int STAGES = 3;
static constexpr int TILE_BYTES  = 128 * 128;          // 16KB per operand tile
static constexpr int B_OFF       = TILE_BYTES;
static constexpr int STAGE_BYTES = 2 * TILE_BYTES;     // 32KB
static constexpr int SMEM_BYTES  = STAGES * STAGE_BYTES;  // 96KB

// ---- pre-split fp16 scratch (device globals; no allocations) ----
__device__ __half g_qry_hi [(size_t)B_ * TQ * HH];
__device__ __half g_qry_lo [(size_t)B_ * TQ * HH];
__device__ __half g_W_hi   [(size_t)HH * HH];
__device__ __half g_W_lo   [(size_t)HH * HH];
__device__ __half g_keys_hi[(size_t)B_ * TK * HH];
__device__ __half g_keys_lo[(size_t)B_ * TK * HH];
__device__ __half g_keysT_hi[(size_t)B_ * HH * TK];
__device__ __half g_keysT_lo[(size_t)B_ * HH * TK];
__device__ __half g_q_hi   [(size_t)B_ * TQ * HH];
__device__ __half g_q_lo   [(size_t)B_ * TQ * HH];
__device__ __half g_attn_hi[(size_t)B_ * TQ * TK];
__device__ __half g_attn_lo[(size_t)B_ * TQ * TK];

__device__ __forceinline__ uint32_t smem_u32_of(const void* p) {
    uint32_t a;
    asm("{ .reg .u64 t; cvta.to.shared.u64 t, %1; cvt.u32.u64 %0, t; }"
        : "=r"(a) : "l"(p));
    return a;
}

__device__ __forceinline__ void cp_async16(uint32_t dst, const void* src) {
    asm volatile("cp.async.cg.shared.global [%0], [%1], 16;"
                 :: "r"(dst), "l"(src) : "memory");
}
#define CP_COMMIT() asm volatile("cp.async.commit_group;" ::: "memory")
#define CP_WAIT(n)  asm volatile("cp.async.wait_group %0;" :: "n"(n) : "memory")

__device__ __forceinline__ void mma_f16(float* d, const uint32_t* a, const uint32_t* b) {
    asm volatile(
        "mma.sync.aligned.m16n8k16.row.col.f32.f16.f16.f32 "
        "{%0,%1,%2,%3}, {%4,%5,%6,%7}, {%8,%9}, {%0,%1,%2,%3};"
        : "+f"(d[0]), "+f"(d[1]), "+f"(d[2]), "+f"(d[3])
        : "r"(a[0]), "r"(a[1]), "r"(a[2]), "r"(a[3]), "r"(b[0]), "r"(b[1]));
}

__device__ __forceinline__ void ldsm_x4(uint32_t* r, uint32_t saddr) {
    asm volatile("ldmatrix.sync.aligned.m8n8.x4.shared.b16 {%0,%1,%2,%3}, [%4];"
                 : "=r"(r[0]), "=r"(r[1]), "=r"(r[2]), "=r"(r[3]) : "r"(saddr));
}

// ---------------------------------------------------------------------------
// GEMM kernel. OUT_HILO: write hi/lo fp16 (with bias) instead of fp32.
// ---------------------------------------------------------------------------
template <bool ADD_BIAS, bool OUT_HILO>
__global__ __launch_bounds__(256, 2)
void gemm_hilo(const __half* __restrict__ Ahi, const __half* __restrict__ Alo,
               const __half* __restrict__ Bhi, const __half* __restrict__ Blo,
               const float* __restrict__ bias,
               float* __restrict__ Cf, __half* __restrict__ Chi, __half* __restrict__ Clo,
               int M, int N, int K,
               long long sA, long long sB, long long sC)
{
    extern __shared__ char sm[];
    const uint32_t smem_base = smem_u32_of(sm);

    const int tid  = threadIdx.x;
    const int wid  = tid >> 5;
    const int lane = tid & 31;
    const int grp  = lane >> 2;
    const int quad = lane & 3;

    const int wm = (wid & 1) * 64;
    const int wn = (wid >> 1) * 32;

    const __half* Ah_g = Ahi + (long long)blockIdx.z * sA;
    const __half* Al_g = Alo + (long long)blockIdx.z * sA;
    const __half* Bh_g = Bhi + (long long)blockIdx.z * sB;
    const __half* Bl_g = Blo + (long long)blockIdx.z * sB;
    const int m0 = blockIdx.y * BM;
    const int n0 = blockIdx.x * BN;
    const int S  = K / BK;

    auto load_stage = [&](int s, int buf) {
        const int k0 = s * BK;
        const uint32_t sb = smem_base + (uint32_t)(buf * STAGE_BYTES);
        #pragma unroll
        for (int i = 0; i < 4; ++i) {
            const int id  = tid + i * 256;
            const int row = id >> 3;
            const int c   = id & 7;
            const __half* src = ((c < 4) ? Ah_g : Al_g)
                              + (long long)(m0 + row) * K + k0 + (c & 3) * 8;
            cp_async16(sb + (uint32_t)(row * 128 + ((c ^ (row & 7)) << 4)), src);
        }
        #pragma unroll
        for (int i = 0; i < 4; ++i) {
            const int id  = tid + i * 256;
            const int row = id >> 3;
            const int c   = id & 7;
            const __half* src = ((c < 4) ? Bh_g : Bl_g)
                              + (long long)(n0 + row) * K + k0 + (c & 3) * 8;
            cp_async16(sb + (uint32_t)(B_OFF + row * 128 + ((c ^ (row & 7)) << 4)), src);
        }
    };

    // ---- ldmatrix lane addressing ----
    const int a_rowl = lane & 15;
    const int a_cb   = (lane >> 4) & 1;
    const int b_rowl = (lane & 7) + ((lane & 16) ? 8 : 0);
    const int b_cb   = (lane >> 3) & 1;

    uint32_t a_ro[4]; int a_rm[4];
    #pragma unroll
    for (int mf = 0; mf < 4; ++mf) {
        const int row = wm + mf * 16 + a_rowl;
        a_ro[mf] = (uint32_t)(row * 128);
        a_rm[mf] = row & 7;
    }
    uint32_t b_ro[2]; int b_rm[2];
    #pragma unroll
    for (int np = 0; np < 2; ++np) {
        const int row = wn + np * 16 + b_rowl;
        b_ro[np] = (uint32_t)(B_OFF + row * 128);
        b_rm[np] = row & 7;
    }

    float acc[4][4][4] = {};

    load_stage(0, 0); CP_COMMIT();
    if (S > 1) { load_stage(1, 1); CP_COMMIT(); }
    CP_WAIT(1);
    __syncthreads();

    for (int s = 0; s < S; ++s) {
        const int buf = s % 3;
        const uint32_t sb = smem_base + (uint32_t)(buf * STAGE_BYTES);

        #pragma unroll
        for (int k16 = 0; k16 < BK / 16; ++k16) {
            uint32_t ah[4][4], al[4][4], bhv[2][4], blv[2][4];
            #pragma unroll
            for (int mf = 0; mf < 4; ++mf) {
                const int ch = a_cb + 2 * k16;
                ldsm_x4(ah[mf], sb + a_ro[mf] + (uint32_t)(((ch)     ^ a_rm[mf]) << 4));
                ldsm_x4(al[mf], sb + a_ro[mf] + (uint32_t)(((ch + 4) ^ a_rm[mf]) << 4));
            }
            #pragma unroll
            for (int np = 0; np < 2; ++np) {
                const int ch = b_cb + 2 * k16;
                ldsm_x4(bhv[np], sb + b_ro[np] + (uint32_t)(((ch)     ^ b_rm[np]) << 4));
                ldsm_x4(blv[np], sb + b_ro[np] + (uint32_t)(((ch + 4) ^ b_rm[np]) << 4));
            }
            #pragma unroll
            for (int mf = 0; mf < 4; ++mf)
                #pragma unroll
                for (int nf = 0; nf < 4; ++nf) {
                    const int np = nf >> 1;
                    const int rp = (nf & 1) * 2;
                    mma_f16(acc[mf][nf], ah[mf], &bhv[np][rp]);
                    mma_f16(acc[mf][nf], ah[mf], &blv[np][rp]);
                    mma_f16(acc[mf][nf], al[mf], &bhv[np][rp]);
                }
        }

        if (s + 2 < S) { load_stage(s + 2, (s + 2) % 3); CP_COMMIT(); CP_WAIT(1); }
        else           { CP_WAIT(0); }
        __syncthreads();
    }

    // ---- epilogue (sequential per fragment to limit live regs) ----
    #pragma unroll
    for (int mf = 0; mf < 4; ++mf) {
        #pragma unroll
        for (int nf = 0; nf < 4; ++nf) {
            const int r = m0 + wm + mf * 16 + grp;
            const int c = n0 + wn + nf * 8 + quad * 2;
            float v0 = acc[mf][nf][0], v1 = acc[mf][nf][1];
            float v2 = acc[mf][nf][2], v3 = acc[mf][nf][3];
            if (ADD_BIAS) {
                const float b0 = bias[c], b1 = bias[c + 1];
                v0 += b0; v1 += b1; v2 += b0; v3 += b1;
            }
            if (OUT_HILO) {
                const long long o0 = (long long)r * N + c + (long long)blockIdx.z * sC;
                const long long o1 = (long long)(r + 8) * N + c + (long long)blockIdx.z * sC;
                __half2 h0 = __floats2half2_rn(v0, v1);
                __half2 l0 = __floats2half2_rn(v0 - __low2float(h0), v1 - __high2float(h0));
                *(__half2*)(Chi + o0) = h0;
                *(__half2*)(Clo + o0) = l0;
                __half2 h1 = __floats2half2_rn(v2, v3);
                __half2 l1 = __floats2half2_rn(v2 - __low2float(h1), v3 - __high2float(h1));
                *(__half2*)(Chi + o1) = h1;
                *(__half2*)(Clo + o1) = l1;
            } else {
                float* Cb = Cf + (long long)blockIdx.z * sC;
                float2 w0; w0.x = v0; w0.y = v1;
                float2 w1; w1.x = v2; w1.y = v3;
                *(float2*)(Cb + (long long)r * N + c) = w0;
                *(float2*)(Cb + (long long)(r + 8) * N + c) = w1;
            }
        }
    }
}

// ---------------------------------------------------------------------------
// Elementwise fp32 -> hi/lo fp16 split (float4 per thread).
// ---------------------------------------------------------------------------
__global__ __launch_bounds__(256)
void split_f32(const float* __restrict__ in, __half* __restrict__ hi,
               __half* __restrict__ lo, long long n4)
{
    const long long i = (long long)blockIdx.x * 256 + threadIdx.x;
    if (i >= n4) return;
    float4 v = ((const float4*)in)[i];
    __half2 h01 = __floats2half2_rn(v.x, v.y);
    __half2 h23 = __floats2half2_rn(v.z, v.w);
    __half2 l01 = __floats2half2_rn(v.x - __low2float(h01), v.y - __high2float(h01));
    __half2 l23 = __floats2half2_rn(v.z - __low2float(h23), v.w - __high2float(h23));
    ((__half2*)hi)[i * 2]     = h01;
    ((__half2*)hi)[i * 2 + 1] = h23;
    ((__half2*)lo)[i * 2]     = l01;
    ((__half2*)lo)[i * 2 + 1] = l23;
}

// ---------------------------------------------------------------------------
// keys -> keys hi/lo [B,Tk,H]  +  keysT hi/lo [B,H,Tk]
// ---------------------------------------------------------------------------
__global__ __launch_bounds__(256)
void split_keys_all(const float* __restrict__ keys,
                    __half* __restrict__ khi, __half* __restrict__ klo,
                    __half* __restrict__ kThi, __half* __restrict__ kTlo)
{
    __shared__ float tile[32][33];
    const int b  = blockIdx.z;
    const int t0 = blockIdx.x * 32;
    const int h0 = blockIdx.y * 32;
    const int tx = threadIdx.x;
    const int ty = threadIdx.y;
    const float* inb = keys + (long long)b * TK * HH;
    __half* khb  = khi  + (long long)b * TK * HH;
    __half* klb  = klo  + (long long)b * TK * HH;
    __half* kThb = kThi + (long long)b * HH * TK;
    __half* kTlb = kTlo + (long long)b * HH * TK;

    #pragma unroll
    for (int i = 0; i < 32; i += 8) {
        float v = inb[(long long)(t0 + ty + i) * HH + h0 + tx];
        tile[ty + i][tx] = v;
        __half h = __float2half_rn(v);
        khb[(long long)(t0 + ty + i) * HH + h0 + tx] = h;
        klb[(long long)(t0 + ty + i) * HH + h0 + tx] = __float2half_rn(v - __half2float(h));
    }
    __syncthreads();
    #pragma unroll
    for (int i = 0; i < 32; i += 8) {
        float v = tile[tx][ty + i];
        __half h = __float2half_rn(v);
        kThb[(long long)(h0 + ty + i) * TK + t0 + tx] = h;
        kTlb[(long long)(h0 + ty + i) * TK + t0 + tx] = __float2half_rn(v - __half2float(h));
    }
}

// ---------------------------------------------------------------------------
// In-place row softmax over TK=1024; also emits hi/lo fp16 copy.
// ---------------------------------------------------------------------------
__global__ __launch_bounds__(256)
void softmax_rows(float* __restrict__ attn, __half* __restrict__ ahi,
                  __half* __restrict__ alo)
{
    const long long row = blockIdx.x;
    float* p = attn + row * (long long)TK;
    const int tid = threadIdx.x;

    float4 v = reinterpret_cast<float4*>(p)[tid];
    __shared__ float sred[8];

    float m = fmaxf(fmaxf(v.x, v.y), fmaxf(v.z, v.w));
    #pragma unroll
    for (int o = 16; o > 0; o >>= 1)
        m = fmaxf(m, __shfl_xor_sync(0xffffffffu, m, o));
    if ((tid & 31) == 0) sred[tid >> 5] = m;
    __syncthreads();
    if (tid < 32) {
        float t = (tid < 8) ? sred[tid] : -FLT_MAX;
        #pragma unroll
        for (int o = 4; o > 0; o >>= 1)
            t = fmaxf(t, __shfl_xor_sync(0xffffffffu, t, o));
        if (tid == 0) sred[0] = t;
    }
    __syncthreads();
    const float mx = sred[0];
    __syncthreads();

    v.x = __expf(v.x - mx);
    v.y = __expf(v.y - mx);
    v.z = __expf(v.z - mx);
    v.w = __expf(v.w - mx);
    float s = v.x + v.y + v.z + v.w;
    #pragma unroll
    for (int o = 16; o > 0; o >>= 1)
        s += __shfl_xor_sync(0xffffffffu, s, o);
    if ((tid & 31) == 0) sred[tid >> 5] = s;
    __syncthreads();
    if (tid < 32) {
        float t = (tid < 8) ? sred[tid] : 0.0f;
        #pragma unroll
        for (int o = 4; o > 0; o >>= 1)
            t += __shfl_xor_sync(0xffffffffu, t, o);
        if (tid == 0) sred[0] = t;
    }
    __syncthreads();
    const float inv = 1.0f / sred[0];

    v.x *= inv; v.y *= inv; v.z *= inv; v.w *= inv;
    reinterpret_cast<float4*>(p)[tid] = v;

    __half2 h01 = __floats2half2_rn(v.x, v.y);
    __half2 h23 = __floats2half2_rn(v.z, v.w);
    __half2 l01 = __floats2half2_rn(v.x - __low2float(h01), v.y - __high2float(h01));
    __half2 l23 = __floats2half2_rn(v.z - __low2float(h23), v.w - __high2float(h23));
    __half2* hp = (__half2*)(ahi + row * (long long)TK) + tid * 2;
    __half2* lp = (__half2*)(alo + row * (long long)TK) + tid * 2;
    hp[0] = h01; hp[1] = h23;
    lp[0] = l01; lp[1] = l23;
}

// ---------------------------------------------------------------------------
// Launch. Inputs: query [B,Tq,H], keys [B,Tk,H], W [H,H], b [H]
// Output: context [B,Tq,H] then attn_weights [B,Tq,Tk].
// ---------------------------------------------------------------------------
extern "C" void kernel_launch(void* const* d_in, const int* in_sizes, int n_in,
                              void* d_out, int out_size)
{
    const float* query = (const float*)d_in[0];
    const float* keys  = (const float*)d_in[1];
    const float* W     = (const float*)d_in[2];
    const float* bias  = (const float*)d_in[3];

    float* ctx  = (float*)d_out;                     // [B,Tq,H]
    float* attn = ctx + (long long)B_ * TQ * HH;     // [B,Tq,Tk]

    __half *qry_hi, *qry_lo, *W_hi, *W_lo, *keys_hi, *keys_lo;
    __half *keysT_hi, *keysT_lo, *q_hi, *q_lo, *attn_hi, *attn_lo;
    cudaGetSymbolAddress((void**)&qry_hi,  g_qry_hi);
    cudaGetSymbolAddress((void**)&qry_lo,  g_qry_lo);
    cudaGetSymbolAddress((void**)&W_hi,    g_W_hi);
    cudaGetSymbolAddress((void**)&W_lo,    g_W_lo);
    cudaGetSymbolAddress((void**)&keys_hi, g_keys_hi);
    cudaGetSymbolAddress((void**)&keys_lo, g_keys_lo);
    cudaGetSymbolAddress((void**)&keysT_hi, g_keysT_hi);
    cudaGetSymbolAddress((void**)&keysT_lo, g_keysT_lo);
    cudaGetSymbolAddress((void**)&q_hi,    g_q_hi);
    cudaGetSymbolAddress((void**)&q_lo,    g_q_lo);
    cudaGetSymbolAddress((void**)&attn_hi, g_attn_hi);
    cudaGetSymbolAddress((void**)&attn_lo, g_attn_lo);

    cudaFuncSetAttribute((const void*)gemm_hilo<true, true>,
                         cudaFuncAttributeMaxDynamicSharedMemorySize, SMEM_BYTES);
    cudaFuncSetAttribute((const void*)gemm_hilo<false, false>,
                         cudaFuncAttributeMaxDynamicSharedMemorySize, SMEM_BYTES);

    // 0) splits
    {
        long long n4q = (long long)B_ * TQ * HH / 4;
        split_f32<<<(unsigned)((n4q + 255) / 256), 256>>>(query, qry_hi, qry_lo, n4q);
        long long n4w = (long long)HH * HH / 4;
        split_f32<<<(unsigned)((n4w + 255) / 256), 256>>>(W, W_hi, W_lo, n4w);
        split_keys_all<<<dim3(TK / 32, HH / 32, B_), dim3(32, 8)>>>(
            keys, keys_hi, keys_lo, keysT_hi, keysT_lo);
    }

    // 1) q = query @ W^T + b -> q_hi/q_lo fp16
    gemm_hilo<true, true><<<dim3(HH / BN, (B_ * TQ) / BM, 1), 256, SMEM_BYTES>>>(
        qry_hi, qry_lo, W_hi, W_lo, bias,
        nullptr, q_hi, q_lo,
        B_ * TQ, HH, HH, 0, 0, 0);

    // 2) scores = q @ keys^T per batch -> attn fp32
    gemm_hilo<false, false><<<dim3(TK / BN, TQ / BM, B_), 256, SMEM_BYTES>>>(
        q_hi, q_lo, keys_hi, keys_lo, nullptr,
        attn, nullptr, nullptr,
        TQ, TK, HH,
        (long long)TQ * HH, (long long)TK * HH, (long long)TQ * TK);

    // 3) softmax rows in place + emit hi/lo fp16
    softmax_rows<<<B_ * TQ, 256>>>(attn, attn_hi, attn_lo);

    // 4) context = attn @ keysT^T per batch -> ctx fp32
    gemm_hilo<false, false><<<dim3(HH / BN, TQ / BM, B_), 256, SMEM_BYTES>>>(
        attn_hi, attn_lo, keysT_hi, keysT_lo, nullptr,
        ctx, nullptr, nullptr,
        TQ, HH, TK,
        (long long)TQ * TK, (long long)HH * TK, (long long)TQ * HH);
}

// round 9
// speedup vs baseline: 2.6719x; 1.0098x over previous
#include <cuda_runtime.h>
#include <cuda_fp16.h>
#include <float.h>
#include <stdint.h>

// Problem dims (fixed by the reference)
static constexpr int B_  = 32;
static constexpr int TQ  = 1024;
static constexpr int TK  = 1024;
static constexpr int HH  = 512;

// ---------------------------------------------------------------------------
// fp16x3 GEMM, operands pre-split to hi/lo fp16 in gmem.
// C[M,N] = A[M,K]*B[N,K]^T (+bias). CTA 128x128, BK=32, 3-stage cp.async.
// smem row (per tile row): [hi 32h | lo 32h] = 128B, XOR-swizzled by row&7.
// 2 CTAs/SM; MMAs issued term-major (3 sweeps x 16 independent accs) to
// eliminate accumulator RAW chains.
// ---------------------------------------------------------------------------
static constexpr int BM = 128;
static constexpr int BN = 128;
static constexpr int BK = 32;
static constexpr int STAGES = 3;
static constexpr int TILE_BYTES  = 128 * 128;          // 16KB per operand tile
static constexpr int B_OFF       = TILE_BYTES;
static constexpr int STAGE_BYTES = 2 * TILE_BYTES;     // 32KB
static constexpr int SMEM_BYTES  = STAGES * STAGE_BYTES;  // 96KB

// ---- pre-split fp16 scratch (device globals; no allocations) ----
__device__ __half g_qry_hi [(size_t)B_ * TQ * HH];
__device__ __half g_qry_lo [(size_t)B_ * TQ * HH];
__device__ __half g_W_hi   [(size_t)HH * HH];
__device__ __half g_W_lo   [(size_t)HH * HH];
__device__ __half g_keys_hi[(size_t)B_ * TK * HH];
__device__ __half g_keys_lo[(size_t)B_ * TK * HH];
__device__ __half g_keysT_hi[(size_t)B_ * HH * TK];
__device__ __half g_keysT_lo[(size_t)B_ * HH * TK];
__device__ __half g_q_hi   [(size_t)B_ * TQ * HH];
__device__ __half g_q_lo   [(size_t)B_ * TQ * HH];
__device__ __half g_attn_hi[(size_t)B_ * TQ * TK];
__device__ __half g_attn_lo[(size_t)B_ * TQ * TK];

__device__ __forceinline__ uint32_t smem_u32_of(const void* p) {
    uint32_t a;
    asm("{ .reg .u64 t; cvta.to.shared.u64 t, %1; cvt.u32.u64 %0, t; }"
        : "=r"(a) : "l"(p));
    return a;
}

__device__ __forceinline__ void cp_async16(uint32_t dst, const void* src) {
    asm volatile("cp.async.cg.shared.global [%0], [%1], 16;"
                 :: "r"(dst), "l"(src) : "memory");
}
#define CP_COMMIT() asm volatile("cp.async.commit_group;" ::: "memory")
#define CP_WAIT(n)  asm volatile("cp.async.wait_group %0;" :: "n"(n) : "memory")

__device__ __forceinline__ void mma_f16(float* d, const uint32_t* a, const uint32_t* b) {
    asm volatile(
        "mma.sync.aligned.m16n8k16.row.col.f32.f16.f16.f32 "
        "{%0,%1,%2,%3}, {%4,%5,%6,%7}, {%8,%9}, {%0,%1,%2,%3};"
        : "+f"(d[0]), "+f"(d[1]), "+f"(d[2]), "+f"(d[3])
        : "r"(a[0]), "r"(a[1]), "r"(a[2]), "r"(a[3]), "r"(b[0]), "r"(b[1]));
}

__device__ __forceinline__ void ldsm_x4(uint32_t* r, uint32_t saddr) {
    asm volatile("ldmatrix.sync.aligned.m8n8.x4.shared.b16 {%0,%1,%2,%3}, [%4];"
                 : "=r"(r[0]), "=r"(r[1]), "=r"(r[2]), "=r"(r[3]) : "r"(saddr));
}

// ---------------------------------------------------------------------------
// GEMM kernel. OUT_HILO: write hi/lo fp16 (with bias) instead of fp32.
// ---------------------------------------------------------------------------
template <bool ADD_BIAS, bool OUT_HILO>
__global__ __launch_bounds__(256, 2)
void gemm_hilo(const __half* __restrict__ Ahi, const __half* __restrict__ Alo,
               const __half* __restrict__ Bhi, const __half* __restrict__ Blo,
               const float* __restrict__ bias,
               float* __restrict__ Cf, __half* __restrict__ Chi, __half* __restrict__ Clo,
               int M, int N, int K,
               long long sA, long long sB, long long sC)
{
    extern __shared__ char sm[];
    const uint32_t smem_base = smem_u32_of(sm);

    const int tid  = threadIdx.x;
    const int wid  = tid >> 5;
    const int lane = tid & 31;
    const int grp  = lane >> 2;
    const int quad = lane & 3;

    const int wm = (wid & 1) * 64;
    const int wn = (wid >> 1) * 32;

    const __half* Ah_g = Ahi + (long long)blockIdx.z * sA;
    const __half* Al_g = Alo + (long long)blockIdx.z * sA;
    const __half* Bh_g = Bhi + (long long)blockIdx.z * sB;
    const __half* Bl_g = Blo + (long long)blockIdx.z * sB;
    const int m0 = blockIdx.y * BM;
    const int n0 = blockIdx.x * BN;
    const int S  = K / BK;

    auto load_stage = [&](int s, int buf) {
        const int k0 = s * BK;
        const uint32_t sb = smem_base + (uint32_t)(buf * STAGE_BYTES);
        #pragma unroll
        for (int i = 0; i < 4; ++i) {
            const int id  = tid + i * 256;
            const int row = id >> 3;
            const int c   = id & 7;
            const __half* src = ((c < 4) ? Ah_g : Al_g)
                              + (long long)(m0 + row) * K + k0 + (c & 3) * 8;
            cp_async16(sb + (uint32_t)(row * 128 + ((c ^ (row & 7)) << 4)), src);
        }
        #pragma unroll
        for (int i = 0; i < 4; ++i) {
            const int id  = tid + i * 256;
            const int row = id >> 3;
            const int c   = id & 7;
            const __half* src = ((c < 4) ? Bh_g : Bl_g)
                              + (long long)(n0 + row) * K + k0 + (c & 3) * 8;
            cp_async16(sb + (uint32_t)(B_OFF + row * 128 + ((c ^ (row & 7)) << 4)), src);
        }
    };

    // ---- ldmatrix lane addressing ----
    const int a_rowl = lane & 15;
    const int a_cb   = (lane >> 4) & 1;
    const int b_rowl = (lane & 7) + ((lane & 16) ? 8 : 0);
    const int b_cb   = (lane >> 3) & 1;

    uint32_t a_ro[4]; int a_rm[4];
    #pragma unroll
    for (int mf = 0; mf < 4; ++mf) {
        const int row = wm + mf * 16 + a_rowl;
        a_ro[mf] = (uint32_t)(row * 128);
        a_rm[mf] = row & 7;
    }
    uint32_t b_ro[2]; int b_rm[2];
    #pragma unroll
    for (int np = 0; np < 2; ++np) {
        const int row = wn + np * 16 + b_rowl;
        b_ro[np] = (uint32_t)(B_OFF + row * 128);
        b_rm[np] = row & 7;
    }

    float acc[4][4][4] = {};

    load_stage(0, 0); CP_COMMIT();
    if (S > 1) { load_stage(1, 1); CP_COMMIT(); }
    CP_WAIT(1);
    __syncthreads();

    for (int s = 0; s < S; ++s) {
        const int buf = s % 3;
        const uint32_t sb = smem_base + (uint32_t)(buf * STAGE_BYTES);

        #pragma unroll
        for (int k16 = 0; k16 < BK / 16; ++k16) {
            uint32_t ah[4][4], al[4][4], bhv[2][4], blv[2][4];
            #pragma unroll
            for (int mf = 0; mf < 4; ++mf) {
                const int ch = a_cb + 2 * k16;
                ldsm_x4(ah[mf], sb + a_ro[mf] + (uint32_t)(((ch)     ^ a_rm[mf]) << 4));
                ldsm_x4(al[mf], sb + a_ro[mf] + (uint32_t)(((ch + 4) ^ a_rm[mf]) << 4));
            }
            #pragma unroll
            for (int np = 0; np < 2; ++np) {
                const int ch = b_cb + 2 * k16;
                ldsm_x4(bhv[np], sb + b_ro[np] + (uint32_t)(((ch)     ^ b_rm[np]) << 4));
                ldsm_x4(blv[np], sb + b_ro[np] + (uint32_t)(((ch + 4) ^ b_rm[np]) << 4));
            }
            // Term-major sweeps: 16 independent accumulators per sweep,
            // RAW reuse distance on each acc = 16 MMAs.
            #pragma unroll
            for (int mf = 0; mf < 4; ++mf)
                #pragma unroll
                for (int nf = 0; nf < 4; ++nf)
                    mma_f16(acc[mf][nf], ah[mf], &bhv[nf >> 1][(nf & 1) * 2]);
            #pragma unroll
            for (int mf = 0; mf < 4; ++mf)
                #pragma unroll
                for (int nf = 0; nf < 4; ++nf)
                    mma_f16(acc[mf][nf], ah[mf], &blv[nf >> 1][(nf & 1) * 2]);
            #pragma unroll
            for (int mf = 0; mf < 4; ++mf)
                #pragma unroll
                for (int nf = 0; nf < 4; ++nf)
                    mma_f16(acc[mf][nf], al[mf], &bhv[nf >> 1][(nf & 1) * 2]);
        }

        if (s + 2 < S) { load_stage(s + 2, (s + 2) % 3); CP_COMMIT(); CP_WAIT(1); }
        else           { CP_WAIT(0); }
        __syncthreads();
    }

    // ---- epilogue ----
    #pragma unroll
    for (int mf = 0; mf < 4; ++mf) {
        #pragma unroll
        for (int nf = 0; nf < 4; ++nf) {
            const int r = m0 + wm + mf * 16 + grp;
            const int c = n0 + wn + nf * 8 + quad * 2;
            float v0 = acc[mf][nf][0], v1 = acc[mf][nf][1];
            float v2 = acc[mf][nf][2], v3 = acc[mf][nf][3];
            if (ADD_BIAS) {
                const float b0 = bias[c], b1 = bias[c + 1];
                v0 += b0; v1 += b1; v2 += b0; v3 += b1;
            }
            if (OUT_HILO) {
                const long long o0 = (long long)r * N + c + (long long)blockIdx.z * sC;
                const long long o1 = (long long)(r + 8) * N + c + (long long)blockIdx.z * sC;
                __half2 h0 = __floats2half2_rn(v0, v1);
                __half2 l0 = __floats2half2_rn(v0 - __low2float(h0), v1 - __high2float(h0));
                *(__half2*)(Chi + o0) = h0;
                *(__half2*)(Clo + o0) = l0;
                __half2 h1 = __floats2half2_rn(v2, v3);
                __half2 l1 = __floats2half2_rn(v2 - __low2float(h1), v3 - __high2float(h1));
                *(__half2*)(Chi + o1) = h1;
                *(__half2*)(Clo + o1) = l1;
            } else {
                float* Cb = Cf + (long long)blockIdx.z * sC;
                float2 w0; w0.x = v0; w0.y = v1;
                float2 w1; w1.x = v2; w1.y = v3;
                *(float2*)(Cb + (long long)r * N + c) = w0;
                *(float2*)(Cb + (long long)(r + 8) * N + c) = w1;
            }
        }
    }
}

// ---------------------------------------------------------------------------
// Elementwise fp32 -> hi/lo fp16 split (float4 per thread).
// ---------------------------------------------------------------------------
__global__ __launch_bounds__(256)
void split_f32(const float* __restrict__ in, __half* __restrict__ hi,
               __half* __restrict__ lo, long long n4)
{
    const long long i = (long long)blockIdx.x * 256 + threadIdx.x;
    if (i >= n4) return;
    float4 v = ((const float4*)in)[i];
    __half2 h01 = __floats2half2_rn(v.x, v.y);
    __half2 h23 = __floats2half2_rn(v.z, v.w);
    __half2 l01 = __floats2half2_rn(v.x - __low2float(h01), v.y - __high2float(h01));
    __half2 l23 = __floats2half2_rn(v.z - __low2float(h23), v.w - __high2float(h23));
    ((__half2*)hi)[i * 2]     = h01;
    ((__half2*)hi)[i * 2 + 1] = h23;
    ((__half2*)lo)[i * 2]     = l01;
    ((__half2*)lo)[i * 2 + 1] = l23;
}

// ---------------------------------------------------------------------------
// keys -> keys hi/lo [B,Tk,H]  +  keysT hi/lo [B,H,Tk]
// ---------------------------------------------------------------------------
__global__ __launch_bounds__(256)
void split_keys_all(const float* __restrict__ keys,
                    __half* __restrict__ khi, __half* __restrict__ klo,
                    __half* __restrict__ kThi, __half* __restrict__ kTlo)
{
    __shared__ float tile[32][33];
    const int b  = blockIdx.z;
    const int t0 = blockIdx.x * 32;
    const int h0 = blockIdx.y * 32;
    const int tx = threadIdx.x;
    const int ty = threadIdx.y;
    const float* inb = keys + (long long)b * TK * HH;
    __half* khb  = khi  + (long long)b * TK * HH;
    __half* klb  = klo  + (long long)b * TK * HH;
    __half* kThb = kThi + (long long)b * HH * TK;
    __half* kTlb = kTlo + (long long)b * HH * TK;

    #pragma unroll
    for (int i = 0; i < 32; i += 8) {
        float v = inb[(long long)(t0 + ty + i) * HH + h0 + tx];
        tile[ty + i][tx] = v;
        __half h = __float2half_rn(v);
        khb[(long long)(t0 + ty + i) * HH + h0 + tx] = h;
        klb[(long long)(t0 + ty + i) * HH + h0 + tx] = __float2half_rn(v - __half2float(h));
    }
    __syncthreads();
    #pragma unroll
    for (int i = 0; i < 32; i += 8) {
        float v = tile[tx][ty + i];
        __half h = __float2half_rn(v);
        kThb[(long long)(h0 + ty + i) * TK + t0 + tx] = h;
        kTlb[(long long)(h0 + ty + i) * TK + t0 + tx] = __float2half_rn(v - __half2float(h));
    }
}

// ---------------------------------------------------------------------------
// In-place row softmax over TK=1024; also emits hi/lo fp16 copy.
// ---------------------------------------------------------------------------
__global__ __launch_bounds__(256)
void softmax_rows(float* __restrict__ attn, __half* __restrict__ ahi,
                  __half* __restrict__ alo)
{
    const long long row = blockIdx.x;
    float* p = attn + row * (long long)TK;
    const int tid = threadIdx.x;

    float4 v = reinterpret_cast<float4*>(p)[tid];
    __shared__ float sred[8];

    float m = fmaxf(fmaxf(v.x, v.y), fmaxf(v.z, v.w));
    #pragma unroll
    for (int o = 16; o > 0; o >>= 1)
        m = fmaxf(m, __shfl_xor_sync(0xffffffffu, m, o));
    if ((tid & 31) == 0) sred[tid >> 5] = m;
    __syncthreads();
    if (tid < 32) {
        float t = (tid < 8) ? sred[tid] : -FLT_MAX;
        #pragma unroll
        for (int o = 4; o > 0; o >>= 1)
            t = fmaxf(t, __shfl_xor_sync(0xffffffffu, t, o));
        if (tid == 0) sred[0] = t;
    }
    __syncthreads();
    const float mx = sred[0];
    __syncthreads();

    v.x = __expf(v.x - mx);
    v.y = __expf(v.y - mx);
    v.z = __expf(v.z - mx);
    v.w = __expf(v.w - mx);
    float s = v.x + v.y + v.z + v.w;
    #pragma unroll
    for (int o = 16; o > 0; o >>= 1)
        s += __shfl_xor_sync(0xffffffffu, s, o);
    if ((tid & 31) == 0) sred[tid >> 5] = s;
    __syncthreads();
    if (tid < 32) {
        float t = (tid < 8) ? sred[tid] : 0.0f;
        #pragma unroll
        for (int o = 4; o > 0; o >>= 1)
            t += __shfl_xor_sync(0xffffffffu, t, o);
        if (tid == 0) sred[0] = t;
    }
    __syncthreads();
    const float inv = 1.0f / sred[0];

    v.x *= inv; v.y *= inv; v.z *= inv; v.w *= inv;
    reinterpret_cast<float4*>(p)[tid] = v;

    __half2 h01 = __floats2half2_rn(v.x, v.y);
    __half2 h23 = __floats2half2_rn(v.z, v.w);
    __half2 l01 = __floats2half2_rn(v.x - __low2float(h01), v.y - __high2float(h01));
    __half2 l23 = __floats2half2_rn(v.z - __low2float(h23), v.w - __high2float(h23));
    __half2* hp = (__half2*)(ahi + row * (long long)TK) + tid * 2;
    __half2* lp = (__half2*)(alo + row * (long long)TK) + tid * 2;
    hp[0] = h01; hp[1] = h23;
    lp[0] = l01; lp[1] = l23;
}

// ---------------------------------------------------------------------------
// Launch. Inputs: query [B,Tq,H], keys [B,Tk,H], W [H,H], b [H]
// Output: context [B,Tq,H] then attn_weights [B,Tq,Tk].
// ---------------------------------------------------------------------------
extern "C" void kernel_launch(void* const* d_in, const int* in_sizes, int n_in,
                              void* d_out, int out_size)
{
    const float* query = (const float*)d_in[0];
    const float* keys  = (const float*)d_in[1];
    const float* W     = (const float*)d_in[2];
    const float* bias  = (const float*)d_in[3];

    float* ctx  = (float*)d_out;                     // [B,Tq,H]
    float* attn = ctx + (long long)B_ * TQ * HH;     // [B,Tq,Tk]

    __half *qry_hi, *qry_lo, *W_hi, *W_lo, *keys_hi, *keys_lo;
    __half *keysT_hi, *keysT_lo, *q_hi, *q_lo, *attn_hi, *attn_lo;
    cudaGetSymbolAddress((void**)&qry_hi,  g_qry_hi);
    cudaGetSymbolAddress((void**)&qry_lo,  g_qry_lo);
    cudaGetSymbolAddress((void**)&W_hi,    g_W_hi);
    cudaGetSymbolAddress((void**)&W_lo,    g_W_lo);
    cudaGetSymbolAddress((void**)&keys_hi, g_keys_hi);
    cudaGetSymbolAddress((void**)&keys_lo, g_keys_lo);
    cudaGetSymbolAddress((void**)&keysT_hi, g_keysT_hi);
    cudaGetSymbolAddress((void**)&keysT_lo, g_keysT_lo);
    cudaGetSymbolAddress((void**)&q_hi,    g_q_hi);
    cudaGetSymbolAddress((void**)&q_lo,    g_q_lo);
    cudaGetSymbolAddress((void**)&attn_hi, g_attn_hi);
    cudaGetSymbolAddress((void**)&attn_lo, g_attn_lo);

    cudaFuncSetAttribute((const void*)gemm_hilo<true, true>,
                         cudaFuncAttributeMaxDynamicSharedMemorySize, SMEM_BYTES);
    cudaFuncSetAttribute((const void*)gemm_hilo<false, false>,
                         cudaFuncAttributeMaxDynamicSharedMemorySize, SMEM_BYTES);

    // 0) splits
    {
        long long n4q = (long long)B_ * TQ * HH / 4;
        split_f32<<<(unsigned)((n4q + 255) / 256), 256>>>(query, qry_hi, qry_lo, n4q);
        long long n4w = (long long)HH * HH / 4;
        split_f32<<<(unsigned)((n4w + 255) / 256), 256>>>(W, W_hi, W_lo, n4w);
        split_keys_all<<<dim3(TK / 32, HH / 32, B_), dim3(32, 8)>>>(
            keys, keys_hi, keys_lo, keysT_hi, keysT_lo);
    }

    // 1) q = query @ W^T + b -> q_hi/q_lo fp16
    gemm_hilo<true, true><<<dim3(HH / BN, (B_ * TQ) / BM, 1), 256, SMEM_BYTES>>>(
        qry_hi, qry_lo, W_hi, W_lo, bias,
        nullptr, q_hi, q_lo,
        B_ * TQ, HH, HH, 0, 0, 0);

    // 2) scores = q @ keys^T per batch -> attn fp32
    gemm_hilo<false, false><<<dim3(TK / BN, TQ / BM, B_), 256, SMEM_BYTES>>>(
        q_hi, q_lo, keys_hi, keys_lo, nullptr,
        attn, nullptr, nullptr,
        TQ, TK, HH,
        (long long)TQ * HH, (long long)TK * HH, (long long)TQ * TK);

    // 3) softmax rows in place + emit hi/lo fp16
    softmax_rows<<<B_ * TQ, 256>>>(attn, attn_hi, attn_lo);

    // 4) context = attn @ keysT^T per batch -> ctx fp32
    gemm_hilo<false, false><<<dim3(HH / BN, TQ / BM, B_), 256, SMEM_BYTES>>>(
        attn_hi, attn_lo, keysT_hi, keysT_lo, nullptr,
        ctx, nullptr, nullptr,
        TQ, HH, TK,
        (long long)TQ * TK, (long long)HH * TK, (long long)TQ * HH);
}